// round 8
// baseline (speedup 1.0000x reference)
#include <cuda_runtime.h>
#include <cstdint>
#include <cfloat>

// Problem constants
#define BATCH   2
#define SEQ     2048
#define DMODEL  1024
#define NHEADS  16
#define HDIM    64
#define QKV_LD  3072
#define NTOK    (BATCH * SEQ)      // 4096
#define WINDOW  128
#define STRIDE  64

// Scratch (device globals: no allocation allowed)
__device__ float g_qkv[(size_t)NTOK * QKV_LD];    // 4096 x 3072
__device__ float g_y[(size_t)NTOK * DMODEL];      // 4096 x 1024 (tf32-rounded)
__device__ float g_xa[(size_t)NTOK * DMODEL];     // x, tf32-rounded
__device__ float g_wqkv[(size_t)DMODEL * QKV_LD]; // Wqkv, tf32-rounded
__device__ float g_wp[(size_t)DMODEL * DMODEL];   // Wproj, tf32-rounded

__device__ __forceinline__ unsigned f2tf(float f) {
    unsigned u;
    asm("cvt.rna.tf32.f32 %0, %1;" : "=r"(u) : "f"(f));
    return u;
}
__device__ __forceinline__ float4 cvt4(float4 v) {
    float4 t;
    t.x = __uint_as_float(f2tf(v.x));
    t.y = __uint_as_float(f2tf(v.y));
    t.z = __uint_as_float(f2tf(v.z));
    t.w = __uint_as_float(f2tf(v.w));
    return t;
}

// ---------------------------------------------------------------------------
// Fused tf32 pre-round for all three inputs (ONE launch).
// ---------------------------------------------------------------------------
__global__ __launch_bounds__(256) void cvt_all(
    const float4* __restrict__ a, float4* __restrict__ oa, int na,
    const float4* __restrict__ b, float4* __restrict__ ob, int nb,
    const float4* __restrict__ c, float4* __restrict__ oc, int nc)
{
    const int total = na + nb + nc;
    for (int i = blockIdx.x * blockDim.x + threadIdx.x; i < total;
         i += gridDim.x * blockDim.x) {
        if (i < na)            oa[i]          = cvt4(a[i]);
        else if (i < na + nb)  ob[i - na]     = cvt4(b[i - na]);
        else                   oc[i - na - nb] = cvt4(c[i - na - nb]);
    }
}

// ===========================================================================
// TF32 mma.sync GEMM v5: cp.async 3-stage ring, BK=32 (4 ks per barrier),
// fragment double-buffering across ks steps. Inputs pre-rounded to tf32.
// CTA 256x128, 256 threads = 8 warps (4M x 2N), warp tile 64x64.
// A via ldmatrix.x4 (tf32 b16-pair trick), pitch 36 (conflict-free);
// B via scalar LDS, pitch 136 (banks 8k+n distinct).
// Requires M%256==0, N%128==0, K%32==0.
// ===========================================================================
#define BM 256
#define BN 128
#define BK 32
#define AP 36    // A row pitch (floats): 144B stride -> ldmatrix conflict-free
#define BP 136   // B row pitch (floats)
#define STAGES 3
#define STG_A (BM * AP)          // 9216 floats
#define STG_B (BK * BP)          // 4352 floats
#define GEMM_SMEM (STAGES * (STG_A + STG_B) * (int)sizeof(float))  // 162816 B

__device__ __forceinline__ void cp16(uint32_t dst, const float* src) {
    asm volatile("cp.async.ca.shared.global [%0], [%1], 16;"
                 :: "r"(dst), "l"(src) : "memory");
}

// 256-thread stage issue for a 256x32 A tile + 32x128 B tile.
__device__ __forceinline__ void issue_stage(
    const float* __restrict__ A, const float* __restrict__ B,
    float* As, float* Bs, int row0, int col0, int k0, int tid, int N, int K)
{
    // A: one row per thread, 8 x 16B
    const float* ap = A + (size_t)(row0 + tid) * K + k0;
    uint32_t da = (uint32_t)__cvta_generic_to_shared(&As[tid * AP]);
#pragma unroll
    for (int j = 0; j < 8; ++j) cp16(da + j * 16, ap + j * 4);

    // B: row = tid>>3 (0..31), 16 consecutive floats per thread
    const int bk = tid >> 3;
    const int bn = (tid & 7) * 16;
    const float* bp = B + (size_t)(k0 + bk) * N + col0 + bn;
    uint32_t db = (uint32_t)__cvta_generic_to_shared(&Bs[bk * BP + bn]);
#pragma unroll
    for (int j = 0; j < 4; ++j) cp16(db + j * 16, bp + j * 4);
}

__global__ __launch_bounds__(256, 1) void tgemm(
    const float* __restrict__ A, const float* __restrict__ B,
    float* __restrict__ C, int M, int N, int K)
{
    extern __shared__ float sm[];
    float* As0 = sm;                       // [STAGES][STG_A]  ([m][k])
    float* Bs0 = sm + STAGES * STG_A;      // [STAGES][STG_B]  ([k][n])

    const int tid  = threadIdx.x;
    const int lane = tid & 31;
    const int wid  = tid >> 5;
    const int warp_m = wid >> 1;           // 0..3
    const int warp_n = wid & 1;            // 0..1
    const int row0 = blockIdx.y * BM;
    const int col0 = blockIdx.x * BN;

    float acc[4][8][4];
#pragma unroll
    for (int mi = 0; mi < 4; ++mi)
#pragma unroll
        for (int ni = 0; ni < 8; ++ni)
#pragma unroll
            for (int e = 0; e < 4; ++e) acc[mi][ni][e] = 0.0f;

    const int nk = K / BK;

    // prologue: issue 2 stages
#pragma unroll
    for (int s = 0; s < STAGES - 1; ++s) {
        issue_stage(A, B, As0 + s * STG_A, Bs0 + s * STG_B,
                    row0, col0, s * BK, tid, N, K);
        asm volatile("cp.async.commit_group;" ::: "memory");
    }

    const int lrow = lane & 15;
    const int lk4  = (lane & 16) ? 4 : 0;
    const int bkr  = lane & 3;
    const int bnc  = warp_n * 64 + (lane >> 2);

    // fragment double buffers
    unsigned af[2][4][4];
    unsigned b0f[2][8], b1f[2][8];

    int cur = 0;
    for (int it = 0; it < nk; ++it) {
        asm volatile("cp.async.wait_group 1;" ::: "memory");
        __syncthreads();

        // issue chunk it+2 into the buffer freed by chunk it-1
        if (it + STAGES - 1 < nk) {
            const int nb = (cur + STAGES - 1) % STAGES;
            issue_stage(A, B, As0 + nb * STG_A, Bs0 + nb * STG_B,
                        row0, col0, (it + STAGES - 1) * BK, tid, N, K);
        }
        asm volatile("cp.async.commit_group;" ::: "memory");

        const float*   Ac  = As0 + cur * STG_A;
        const float*   Bc  = Bs0 + cur * STG_B;
        const unsigned smA = (unsigned)__cvta_generic_to_shared(Ac);

        // ---- compute chunk: 4 ks steps, fragments double-buffered ----
        // load ks=0 into buf 0
#pragma unroll
        for (int mi = 0; mi < 4; ++mi) {
            unsigned ad = smA + (((warp_m * 64 + mi * 16 + lrow) * AP + lk4) << 2);
            asm volatile(
                "ldmatrix.sync.aligned.m8n8.x4.shared.b16 {%0,%1,%2,%3}, [%4];"
                : "=r"(af[0][mi][0]), "=r"(af[0][mi][1]),
                  "=r"(af[0][mi][2]), "=r"(af[0][mi][3])
                : "r"(ad));
        }
#pragma unroll
        for (int ni = 0; ni < 8; ++ni) {
            b0f[0][ni] = __float_as_uint(Bc[bkr * BP + bnc + ni * 8]);
            b1f[0][ni] = __float_as_uint(Bc[(bkr + 4) * BP + bnc + ni * 8]);
        }

#pragma unroll
        for (int ks = 0; ks < 4; ++ks) {
            const int cb = ks & 1;
            const int nb = cb ^ 1;
            if (ks < 3) {  // prefetch ks+1 fragments
                const int kn = ks + 1;
#pragma unroll
                for (int mi = 0; mi < 4; ++mi) {
                    unsigned ad = smA +
                        (((warp_m * 64 + mi * 16 + lrow) * AP + kn * 8 + lk4) << 2);
                    asm volatile(
                        "ldmatrix.sync.aligned.m8n8.x4.shared.b16 {%0,%1,%2,%3}, [%4];"
                        : "=r"(af[nb][mi][0]), "=r"(af[nb][mi][1]),
                          "=r"(af[nb][mi][2]), "=r"(af[nb][mi][3])
                        : "r"(ad));
                }
                const int krow = kn * 8 + bkr;
#pragma unroll
                for (int ni = 0; ni < 8; ++ni) {
                    b0f[nb][ni] = __float_as_uint(Bc[krow * BP + bnc + ni * 8]);
                    b1f[nb][ni] = __float_as_uint(Bc[(krow + 4) * BP + bnc + ni * 8]);
                }
            }
#pragma unroll
            for (int mi = 0; mi < 4; ++mi)
#pragma unroll
                for (int ni = 0; ni < 8; ++ni) {
                    asm volatile(
                        "mma.sync.aligned.m16n8k8.row.col.f32.tf32.tf32.f32 "
                        "{%0,%1,%2,%3}, {%4,%5,%6,%7}, {%8,%9}, {%0,%1,%2,%3};"
                        : "+f"(acc[mi][ni][0]), "+f"(acc[mi][ni][1]),
                          "+f"(acc[mi][ni][2]), "+f"(acc[mi][ni][3])
                        : "r"(af[cb][mi][0]), "r"(af[cb][mi][1]),
                          "r"(af[cb][mi][2]), "r"(af[cb][mi][3]),
                          "r"(b0f[cb][ni]), "r"(b1f[cb][ni]));
                }
        }

        cur = (cur + 1) % STAGES;
    }

    // ---- epilogue ----
    const int g  = lane >> 2;
    const int tg = lane & 3;
#pragma unroll
    for (int mi = 0; mi < 4; ++mi) {
#pragma unroll
        for (int ni = 0; ni < 8; ++ni) {
            const int row = row0 + warp_m * 64 + mi * 16 + g;
            const int col = col0 + warp_n * 64 + ni * 8 + 2 * tg;
            *(float2*)&C[(size_t)row * N + col] =
                make_float2(acc[mi][ni][0], acc[mi][ni][1]);
            *(float2*)&C[(size_t)(row + 8) * N + col] =
                make_float2(acc[mi][ni][2], acc[mi][ni][3]);
        }
    }
}

// ---------------------------------------------------------------------------
// Sparse flash attention (R1 logic; epilogue writes tf32-rounded y).
// ---------------------------------------------------------------------------
#define APITCH 68
#define ATTN_SMEM (4 * 64 * APITCH * (int)sizeof(float))

__global__ __launch_bounds__(256) void sparse_attn(
    const float* __restrict__ qkv, float* __restrict__ y)
{
    extern __shared__ float smf[];
    float* Qt = smf;
    float* Kt = Qt + 64 * APITCH;
    float* Vs = Kt + 64 * APITCH;
    float* Ps = Vs + 64 * APITCH;

    const int t   = blockIdx.x;
    const int h   = blockIdx.y;
    const int b   = blockIdx.z;
    const int tid = threadIdx.x;
    const int tx  = tid & 15;
    const int ty  = tid >> 4;
    const int r0  = t * 64;

    const size_t base = (size_t)b * SEQ * QKV_LD;

    for (int e = tid; e < 1024; e += 256) {
        const int tok = e >> 4;
        const int d4  = (e & 15) * 4;
        float4 v = *(const float4*)(qkv + base + (size_t)(r0 + tok) * QKV_LD + h * HDIM + d4);
        Qt[(d4 + 0) * APITCH + tok] = v.x;
        Qt[(d4 + 1) * APITCH + tok] = v.y;
        Qt[(d4 + 2) * APITCH + tok] = v.z;
        Qt[(d4 + 3) * APITCH + tok] = v.w;
    }

    float m_i[4], l_i[4], acc[4][4];
#pragma unroll
    for (int i = 0; i < 4; ++i) {
        m_i[i] = -3.0e38f;
        l_i[i] = 0.0f;
#pragma unroll
        for (int j = 0; j < 4; ++j) acc[i][j] = 0.0f;
    }

    const int kb_start = (t >= 2) ? (t - 2) : 0;
    const int n_win    = t - kb_start + 1;
    const int nglob    = (t >= 3) ? (t - 2) : 0;
    const int n_tiles  = n_win + (nglob > 0 ? 1 : 0);

    for (int it = 0; it < n_tiles; ++it) {
        const bool is_glob = (it == n_win);
        const int  kcol0   = (kb_start + it) * 64;

        __syncthreads();

        for (int e = tid; e < 1024; e += 256) {
            const int tok = e >> 4;
            const int d4  = (e & 15) * 4;
            int key;
            bool valid;
            if (is_glob) { key = tok * STRIDE; valid = (tok < nglob); }
            else         { key = kcol0 + tok;  valid = true; }
            float4 kv, vv;
            if (valid) {
                const float* kp = qkv + base + (size_t)key * QKV_LD + DMODEL + h * HDIM + d4;
                kv = *(const float4*)kp;
                vv = *(const float4*)(kp + DMODEL);
            } else {
                kv = make_float4(0.f, 0.f, 0.f, 0.f);
                vv = kv;
            }
            Kt[(d4 + 0) * APITCH + tok] = kv.x;
            Kt[(d4 + 1) * APITCH + tok] = kv.y;
            Kt[(d4 + 2) * APITCH + tok] = kv.z;
            Kt[(d4 + 3) * APITCH + tok] = kv.w;
            *(float4*)&Vs[tok * APITCH + d4] = vv;
        }
        __syncthreads();

        float s[4][4];
#pragma unroll
        for (int i = 0; i < 4; ++i)
#pragma unroll
            for (int j = 0; j < 4; ++j) s[i][j] = 0.0f;

#pragma unroll 8
        for (int k = 0; k < 64; ++k) {
            float4 q4 = *(const float4*)&Qt[k * APITCH + ty * 4];
            float4 k4 = *(const float4*)&Kt[k * APITCH + tx * 4];
            float qa[4] = {q4.x, q4.y, q4.z, q4.w};
            float ka[4] = {k4.x, k4.y, k4.z, k4.w};
#pragma unroll
            for (int i = 0; i < 4; ++i)
#pragma unroll
                for (int j = 0; j < 4; ++j)
                    s[i][j] = fmaf(qa[i], ka[j], s[i][j]);
        }

#pragma unroll
        for (int i = 0; i < 4; ++i) {
            const int row = r0 + ty * 4 + i;
#pragma unroll
            for (int j = 0; j < 4; ++j) {
                bool ok;
                if (is_glob) {
                    ok = (tx * 4 + j) < nglob;
                } else {
                    const int col = kcol0 + tx * 4 + j;
                    ok = (col <= row) && ((row - col) <= (WINDOW - 1) || (col & (STRIDE - 1)) == 0);
                }
                s[i][j] = ok ? s[i][j] * 0.125f : -3.0e38f;
            }
        }

#pragma unroll
        for (int i = 0; i < 4; ++i) {
            float mx = fmaxf(fmaxf(s[i][0], s[i][1]), fmaxf(s[i][2], s[i][3]));
#pragma unroll
            for (int off = 8; off >= 1; off >>= 1)
                mx = fmaxf(mx, __shfl_xor_sync(0xffffffffu, mx, off, 16));
            const float mnew = fmaxf(m_i[i], mx);
            const float alpha = __expf(m_i[i] - mnew);
            float rs = 0.0f;
#pragma unroll
            for (int j = 0; j < 4; ++j) {
                const float p = __expf(s[i][j] - mnew);
                Ps[(ty * 4 + i) * APITCH + tx * 4 + j] = p;
                rs += p;
            }
#pragma unroll
            for (int off = 8; off >= 1; off >>= 1)
                rs += __shfl_xor_sync(0xffffffffu, rs, off, 16);
            l_i[i] = l_i[i] * alpha + rs;
            m_i[i] = mnew;
#pragma unroll
            for (int j = 0; j < 4; ++j) acc[i][j] *= alpha;
        }
        __syncthreads();

#pragma unroll 8
        for (int j = 0; j < 64; ++j) {
            float4 v4 = *(const float4*)&Vs[j * APITCH + tx * 4];
            float va[4] = {v4.x, v4.y, v4.z, v4.w};
            float pa[4];
#pragma unroll
            for (int i = 0; i < 4; ++i) pa[i] = Ps[(ty * 4 + i) * APITCH + j];
#pragma unroll
            for (int i = 0; i < 4; ++i)
#pragma unroll
                for (int d = 0; d < 4; ++d)
                    acc[i][d] = fmaf(pa[i], va[d], acc[i][d]);
        }
    }

    // write y pre-rounded to tf32 (proj GEMM consumes it directly)
#pragma unroll
    for (int i = 0; i < 4; ++i) {
        const float inv = 1.0f / l_i[i];
        const size_t row = (size_t)b * SEQ + r0 + ty * 4 + i;
        float4 o = cvt4(make_float4(acc[i][0] * inv, acc[i][1] * inv,
                                    acc[i][2] * inv, acc[i][3] * inv));
        *(float4*)&y[row * DMODEL + h * HDIM + tx * 4] = o;
    }
}

// ---------------------------------------------------------------------------
extern "C" void kernel_launch(void* const* d_in, const int* in_sizes, int n_in,
                              void* d_out, int out_size)
{
    const float* x     = (const float*)d_in[0];
    const float* Wqkv  = (const float*)d_in[1];
    const float* Wproj = (const float*)d_in[2];
    float* out = (float*)d_out;

    float *qkv = nullptr, *y = nullptr, *xa = nullptr, *wqkv = nullptr, *wp = nullptr;
    cudaGetSymbolAddress((void**)&qkv, g_qkv);
    cudaGetSymbolAddress((void**)&y, g_y);
    cudaGetSymbolAddress((void**)&xa, g_xa);
    cudaGetSymbolAddress((void**)&wqkv, g_wqkv);
    cudaGetSymbolAddress((void**)&wp, g_wp);

    cudaFuncSetAttribute(tgemm, cudaFuncAttributeMaxDynamicSharedMemorySize, GEMM_SMEM);
    cudaFuncSetAttribute(sparse_attn, cudaFuncAttributeMaxDynamicSharedMemorySize, ATTN_SMEM);

    // 0) pre-round all inputs to tf32 in ONE kernel
    cvt_all<<<1184, 256>>>(
        (const float4*)x,     (float4*)xa,   NTOK * DMODEL / 4,
        (const float4*)Wqkv,  (float4*)wqkv, DMODEL * QKV_LD / 4,
        (const float4*)Wproj, (float4*)wp,   DMODEL * DMODEL / 4);

    // 1) QKV projection: [4096,1024] @ [1024,3072]
    tgemm<<<dim3(QKV_LD / BN, NTOK / BM), 256, GEMM_SMEM>>>(xa, wqkv, qkv, NTOK, QKV_LD, DMODEL);

    // 2) Sparse attention (writes tf32-rounded y)
    sparse_attn<<<dim3(SEQ / 64, NHEADS, BATCH), 256, ATTN_SMEM>>>(qkv, y);

    // 3) Output projection: [4096,1024] @ [1024,1024]
    tgemm<<<dim3(DMODEL / BN, NTOK / BM), 256, GEMM_SMEM>>>(y, wp, out, NTOK, DMODEL, DMODEL);
}

// round 9
// speedup vs baseline: 1.0717x; 1.0717x over previous
#include <cuda_runtime.h>
#include <cstdint>
#include <cfloat>

// Problem constants
#define BATCH   2
#define SEQ     2048
#define DMODEL  1024
#define NHEADS  16
#define HDIM    64
#define QKV_LD  3072
#define NTOK    (BATCH * SEQ)      // 4096
#define WINDOW  128
#define STRIDE  64

// Scratch (device globals: no allocation allowed)
__device__ float g_qkv[(size_t)NTOK * QKV_LD];    // 4096 x 3072
__device__ float g_y[(size_t)NTOK * DMODEL];      // 4096 x 1024 (tf32-rounded)
__device__ float g_xa[(size_t)NTOK * DMODEL];     // x, tf32-rounded
__device__ float g_wqkv[(size_t)DMODEL * QKV_LD]; // Wqkv, tf32-rounded
__device__ float g_wp[(size_t)DMODEL * DMODEL];   // Wproj, tf32-rounded

__device__ __forceinline__ unsigned f2tf(float f) {
    unsigned u;
    asm("cvt.rna.tf32.f32 %0, %1;" : "=r"(u) : "f"(f));
    return u;
}
__device__ __forceinline__ float4 cvt4(float4 v) {
    float4 t;
    t.x = __uint_as_float(f2tf(v.x));
    t.y = __uint_as_float(f2tf(v.y));
    t.z = __uint_as_float(f2tf(v.z));
    t.w = __uint_as_float(f2tf(v.w));
    return t;
}

// Fast exp2 on the FMA pipe (x <= 0; clamped at -126). Rel err < 1e-4.
__device__ __forceinline__ float fexp2(float x) {
    x = fmaxf(x, -126.0f);
    float n = floorf(x);
    float f = x - n;
    float p = 0.00133336f;
    p = fmaf(p, f, 0.00961813f);
    p = fmaf(p, f, 0.05550411f);
    p = fmaf(p, f, 0.24022651f);
    p = fmaf(p, f, 0.69314718f);
    p = fmaf(p, f, 1.0f);
    return __int_as_float(((int)n + 127) << 23) * p;
}

// ---------------------------------------------------------------------------
// Fused tf32 pre-round for all three inputs (ONE launch).
// ---------------------------------------------------------------------------
__global__ __launch_bounds__(256) void cvt_all(
    const float4* __restrict__ a, float4* __restrict__ oa, int na,
    const float4* __restrict__ b, float4* __restrict__ ob, int nb,
    const float4* __restrict__ c, float4* __restrict__ oc, int nc)
{
    const int total = na + nb + nc;
    for (int i = blockIdx.x * blockDim.x + threadIdx.x; i < total;
         i += gridDim.x * blockDim.x) {
        if (i < na)            oa[i]           = cvt4(a[i]);
        else if (i < na + nb)  ob[i - na]      = cvt4(b[i - na]);
        else                   oc[i - na - nb] = cvt4(c[i - na - nb]);
    }
}

// ===========================================================================
// TF32 mma.sync GEMM (R6 v4 config — best measured): cp.async 4-stage
// pipeline, inputs pre-rounded to tf32. CTA 256x128, BK=16, 256 threads =
// 8 warps (4M x 2N), warp tile 64x64. A via ldmatrix.x4 (b16-pair trick)
// pitch-20 rows; B via scalar LDS pitch-136.
// ===========================================================================
#define BM 256
#define BN 128
#define BK 16
#define AP 20
#define BP 136
#define STAGES 4
#define STG_A (BM * AP)          // 5120 floats
#define STG_B (BK * BP)          // 2176 floats
#define GEMM_SMEM (STAGES * (STG_A + STG_B) * (int)sizeof(float))  // 116736 B

__device__ __forceinline__ void cp16(uint32_t dst, const float* src) {
    asm volatile("cp.async.ca.shared.global [%0], [%1], 16;"
                 :: "r"(dst), "l"(src) : "memory");
}

__device__ __forceinline__ void issue_stage(
    const float* __restrict__ A, const float* __restrict__ B,
    float* As, float* Bs, int row0, int col0, int k0, int tid, int N, int K)
{
    const int ar = tid >> 1;             // 0..127
    const int ak = (tid & 1) * 8;        // 0 or 8
    // A: 256 rows handled as 2 x 128-row halves, 2 float4 per thread per half
#pragma unroll
    for (int h = 0; h < 2; ++h) {
        const float* ap = A + (size_t)(row0 + h * 128 + ar) * K + k0 + ak;
        uint32_t d = (uint32_t)__cvta_generic_to_shared(&As[(h * 128 + ar) * AP + ak]);
        cp16(d, ap);
        cp16(d + 16, ap + 4);
    }
    const int bk = tid >> 4;             // 0..15
    const int bn = (tid & 15) * 8;       // 0..120
    uint32_t d1 = (uint32_t)__cvta_generic_to_shared(&Bs[bk * BP + bn]);
    const float* bp = B + (size_t)(k0 + bk) * N + col0 + bn;
    cp16(d1, bp);
    cp16(d1 + 16, bp + 4);
}

__global__ __launch_bounds__(256, 1) void tgemm(
    const float* __restrict__ A, const float* __restrict__ B,
    float* __restrict__ C, int M, int N, int K)
{
    extern __shared__ float sm[];
    float* As0 = sm;                       // [STAGES][STG_A]  ([m][k])
    float* Bs0 = sm + STAGES * STG_A;      // [STAGES][STG_B]  ([k][n])

    const int tid  = threadIdx.x;
    const int lane = tid & 31;
    const int wid  = tid >> 5;
    const int warp_m = wid >> 1;           // 0..3
    const int warp_n = wid & 1;            // 0..1
    const int row0 = blockIdx.y * BM;
    const int col0 = blockIdx.x * BN;

    float acc[4][8][4];
#pragma unroll
    for (int mi = 0; mi < 4; ++mi)
#pragma unroll
        for (int ni = 0; ni < 8; ++ni)
#pragma unroll
            for (int e = 0; e < 4; ++e) acc[mi][ni][e] = 0.0f;

    const int nk = K / BK;

#pragma unroll
    for (int s = 0; s < STAGES - 1; ++s) {
        issue_stage(A, B, As0 + s * STG_A, Bs0 + s * STG_B,
                    row0, col0, s * BK, tid, N, K);
        asm volatile("cp.async.commit_group;" ::: "memory");
    }

    const int lrow = lane & 15;
    const int lk4  = (lane & 16) ? 4 : 0;
    const int bkr  = lane & 3;
    const int bnc  = warp_n * 64 + (lane >> 2);

    for (int it = 0; it < nk; ++it) {
        const int cur = it & (STAGES - 1);

        asm volatile("cp.async.wait_group 2;" ::: "memory");
        __syncthreads();

        if (it + STAGES - 1 < nk) {
            const int nb = (it + STAGES - 1) & (STAGES - 1);
            issue_stage(A, B, As0 + nb * STG_A, Bs0 + nb * STG_B,
                        row0, col0, (it + STAGES - 1) * BK, tid, N, K);
        }
        asm volatile("cp.async.commit_group;" ::: "memory");

        const float*   Ac  = As0 + cur * STG_A;
        const float*   Bc  = Bs0 + cur * STG_B;
        const unsigned smA = (unsigned)__cvta_generic_to_shared(Ac);
#pragma unroll
        for (int ks = 0; ks < 2; ++ks) {
            unsigned a[4][4];
#pragma unroll
            for (int mi = 0; mi < 4; ++mi) {
                unsigned ad = smA +
                    (((warp_m * 64 + mi * 16 + lrow) * AP + ks * 8 + lk4) << 2);
                asm volatile(
                    "ldmatrix.sync.aligned.m8n8.x4.shared.b16 {%0,%1,%2,%3}, [%4];"
                    : "=r"(a[mi][0]), "=r"(a[mi][1]), "=r"(a[mi][2]), "=r"(a[mi][3])
                    : "r"(ad));
            }
            unsigned b0[8], b1[8];
            const int krow = ks * 8 + bkr;
#pragma unroll
            for (int ni = 0; ni < 8; ++ni) {
                b0[ni] = __float_as_uint(Bc[krow * BP + bnc + ni * 8]);
                b1[ni] = __float_as_uint(Bc[(krow + 4) * BP + bnc + ni * 8]);
            }
#pragma unroll
            for (int mi = 0; mi < 4; ++mi)
#pragma unroll
                for (int ni = 0; ni < 8; ++ni) {
                    asm volatile(
                        "mma.sync.aligned.m16n8k8.row.col.f32.tf32.tf32.f32 "
                        "{%0,%1,%2,%3}, {%4,%5,%6,%7}, {%8,%9}, {%0,%1,%2,%3};"
                        : "+f"(acc[mi][ni][0]), "+f"(acc[mi][ni][1]),
                          "+f"(acc[mi][ni][2]), "+f"(acc[mi][ni][3])
                        : "r"(a[mi][0]), "r"(a[mi][1]), "r"(a[mi][2]), "r"(a[mi][3]),
                          "r"(b0[ni]), "r"(b1[ni]));
                }
        }
    }

    const int g  = lane >> 2;
    const int tg = lane & 3;
#pragma unroll
    for (int mi = 0; mi < 4; ++mi) {
#pragma unroll
        for (int ni = 0; ni < 8; ++ni) {
            const int row = row0 + warp_m * 64 + mi * 16 + g;
            const int col = col0 + warp_n * 64 + ni * 8 + 2 * tg;
            *(float2*)&C[(size_t)row * N + col] =
                make_float2(acc[mi][ni][0], acc[mi][ni][1]);
            *(float2*)&C[(size_t)(row + 8) * N + col] =
                make_float2(acc[mi][ni][2], acc[mi][ni][3]);
        }
    }
}

// ---------------------------------------------------------------------------
// Sparse flash attention. Softmax in base-2 domain; exp via FMA-pipe poly
// (fexp2) instead of MUFU __expf. Epilogue writes tf32-rounded y.
// ---------------------------------------------------------------------------
#define APITCH 68
#define ATTN_SMEM (4 * 64 * APITCH * (int)sizeof(float))
#define SC2 0.18033688f   // (1/sqrt(64)) * log2(e)

__global__ __launch_bounds__(256) void sparse_attn(
    const float* __restrict__ qkv, float* __restrict__ y)
{
    extern __shared__ float smf[];
    float* Qt = smf;
    float* Kt = Qt + 64 * APITCH;
    float* Vs = Kt + 64 * APITCH;
    float* Ps = Vs + 64 * APITCH;

    const int t   = blockIdx.x;
    const int h   = blockIdx.y;
    const int b   = blockIdx.z;
    const int tid = threadIdx.x;
    const int tx  = tid & 15;
    const int ty  = tid >> 4;
    const int r0  = t * 64;

    const size_t base = (size_t)b * SEQ * QKV_LD;

    for (int e = tid; e < 1024; e += 256) {
        const int tok = e >> 4;
        const int d4  = (e & 15) * 4;
        float4 v = *(const float4*)(qkv + base + (size_t)(r0 + tok) * QKV_LD + h * HDIM + d4);
        Qt[(d4 + 0) * APITCH + tok] = v.x;
        Qt[(d4 + 1) * APITCH + tok] = v.y;
        Qt[(d4 + 2) * APITCH + tok] = v.z;
        Qt[(d4 + 3) * APITCH + tok] = v.w;
    }

    float m_i[4], l_i[4], acc[4][4];
#pragma unroll
    for (int i = 0; i < 4; ++i) {
        m_i[i] = -3.0e38f;
        l_i[i] = 0.0f;
#pragma unroll
        for (int j = 0; j < 4; ++j) acc[i][j] = 0.0f;
    }

    const int kb_start = (t >= 2) ? (t - 2) : 0;
    const int n_win    = t - kb_start + 1;
    const int nglob    = (t >= 3) ? (t - 2) : 0;
    const int n_tiles  = n_win + (nglob > 0 ? 1 : 0);

    for (int it = 0; it < n_tiles; ++it) {
        const bool is_glob = (it == n_win);
        const int  kcol0   = (kb_start + it) * 64;

        __syncthreads();

        for (int e = tid; e < 1024; e += 256) {
            const int tok = e >> 4;
            const int d4  = (e & 15) * 4;
            int key;
            bool valid;
            if (is_glob) { key = tok * STRIDE; valid = (tok < nglob); }
            else         { key = kcol0 + tok;  valid = true; }
            float4 kv, vv;
            if (valid) {
                const float* kp = qkv + base + (size_t)key * QKV_LD + DMODEL + h * HDIM + d4;
                kv = *(const float4*)kp;
                vv = *(const float4*)(kp + DMODEL);
            } else {
                kv = make_float4(0.f, 0.f, 0.f, 0.f);
                vv = kv;
            }
            Kt[(d4 + 0) * APITCH + tok] = kv.x;
            Kt[(d4 + 1) * APITCH + tok] = kv.y;
            Kt[(d4 + 2) * APITCH + tok] = kv.z;
            Kt[(d4 + 3) * APITCH + tok] = kv.w;
            *(float4*)&Vs[tok * APITCH + d4] = vv;
        }
        __syncthreads();

        float s[4][4];
#pragma unroll
        for (int i = 0; i < 4; ++i)
#pragma unroll
            for (int j = 0; j < 4; ++j) s[i][j] = 0.0f;

#pragma unroll 8
        for (int k = 0; k < 64; ++k) {
            float4 q4 = *(const float4*)&Qt[k * APITCH + ty * 4];
            float4 k4 = *(const float4*)&Kt[k * APITCH + tx * 4];
            float qa[4] = {q4.x, q4.y, q4.z, q4.w};
            float ka[4] = {k4.x, k4.y, k4.z, k4.w};
#pragma unroll
            for (int i = 0; i < 4; ++i)
#pragma unroll
                for (int j = 0; j < 4; ++j)
                    s[i][j] = fmaf(qa[i], ka[j], s[i][j]);
        }

        // mask + scale into base-2 domain
#pragma unroll
        for (int i = 0; i < 4; ++i) {
            const int row = r0 + ty * 4 + i;
#pragma unroll
            for (int j = 0; j < 4; ++j) {
                bool ok;
                if (is_glob) {
                    ok = (tx * 4 + j) < nglob;
                } else {
                    const int col = kcol0 + tx * 4 + j;
                    ok = (col <= row) && ((row - col) <= (WINDOW - 1) || (col & (STRIDE - 1)) == 0);
                }
                s[i][j] = ok ? s[i][j] * SC2 : -3.0e38f;
            }
        }

        // online softmax, exp2 on FMA pipe
#pragma unroll
        for (int i = 0; i < 4; ++i) {
            float mx = fmaxf(fmaxf(s[i][0], s[i][1]), fmaxf(s[i][2], s[i][3]));
#pragma unroll
            for (int off = 8; off >= 1; off >>= 1)
                mx = fmaxf(mx, __shfl_xor_sync(0xffffffffu, mx, off, 16));
            const float mnew = fmaxf(m_i[i], mx);
            const float alpha = fexp2(m_i[i] - mnew);
            float rs = 0.0f;
#pragma unroll
            for (int j = 0; j < 4; ++j) {
                const float p = fexp2(s[i][j] - mnew);
                Ps[(ty * 4 + i) * APITCH + tx * 4 + j] = p;
                rs += p;
            }
#pragma unroll
            for (int off = 8; off >= 1; off >>= 1)
                rs += __shfl_xor_sync(0xffffffffu, rs, off, 16);
            l_i[i] = l_i[i] * alpha + rs;
            m_i[i] = mnew;
#pragma unroll
            for (int j = 0; j < 4; ++j) acc[i][j] *= alpha;
        }
        __syncthreads();

#pragma unroll 8
        for (int j = 0; j < 64; ++j) {
            float4 v4 = *(const float4*)&Vs[j * APITCH + tx * 4];
            float va[4] = {v4.x, v4.y, v4.z, v4.w};
            float pa[4];
#pragma unroll
            for (int i = 0; i < 4; ++i) pa[i] = Ps[(ty * 4 + i) * APITCH + j];
#pragma unroll
            for (int i = 0; i < 4; ++i)
#pragma unroll
                for (int d = 0; d < 4; ++d)
                    acc[i][d] = fmaf(pa[i], va[d], acc[i][d]);
        }
    }

    // write y pre-rounded to tf32 (proj GEMM consumes it directly)
#pragma unroll
    for (int i = 0; i < 4; ++i) {
        const float inv = 1.0f / l_i[i];
        const size_t row = (size_t)b * SEQ + r0 + ty * 4 + i;
        float4 o = cvt4(make_float4(acc[i][0] * inv, acc[i][1] * inv,
                                    acc[i][2] * inv, acc[i][3] * inv));
        *(float4*)&y[row * DMODEL + h * HDIM + tx * 4] = o;
    }
}

// ---------------------------------------------------------------------------
extern "C" void kernel_launch(void* const* d_in, const int* in_sizes, int n_in,
                              void* d_out, int out_size)
{
    const float* x     = (const float*)d_in[0];
    const float* Wqkv  = (const float*)d_in[1];
    const float* Wproj = (const float*)d_in[2];
    float* out = (float*)d_out;

    float *qkv = nullptr, *y = nullptr, *xa = nullptr, *wqkv = nullptr, *wp = nullptr;
    cudaGetSymbolAddress((void**)&qkv, g_qkv);
    cudaGetSymbolAddress((void**)&y, g_y);
    cudaGetSymbolAddress((void**)&xa, g_xa);
    cudaGetSymbolAddress((void**)&wqkv, g_wqkv);
    cudaGetSymbolAddress((void**)&wp, g_wp);

    cudaFuncSetAttribute(tgemm, cudaFuncAttributeMaxDynamicSharedMemorySize, GEMM_SMEM);
    cudaFuncSetAttribute(sparse_attn, cudaFuncAttributeMaxDynamicSharedMemorySize, ATTN_SMEM);

    // 0) pre-round all inputs to tf32 in ONE kernel
    cvt_all<<<2368, 256>>>(
        (const float4*)x,     (float4*)xa,   NTOK * DMODEL / 4,
        (const float4*)Wqkv,  (float4*)wqkv, DMODEL * QKV_LD / 4,
        (const float4*)Wproj, (float4*)wp,   DMODEL * DMODEL / 4);

    // 1) QKV projection: [4096,1024] @ [1024,3072]
    tgemm<<<dim3(QKV_LD / BN, NTOK / BM), 256, GEMM_SMEM>>>(xa, wqkv, qkv, NTOK, QKV_LD, DMODEL);

    // 2) Sparse attention (writes tf32-rounded y)
    sparse_attn<<<dim3(SEQ / 64, NHEADS, BATCH), 256, ATTN_SMEM>>>(qkv, y);

    // 3) Output projection: [4096,1024] @ [1024,1024]
    tgemm<<<dim3(DMODEL / BN, NTOK / BM), 256, GEMM_SMEM>>>(y, wp, out, NTOK, DMODEL, DMODEL);
}

// round 10
// speedup vs baseline: 1.3559x; 1.2652x over previous
#include <cuda_runtime.h>
#include <cstdint>
#include <cfloat>

// Problem constants
#define BATCH   2
#define SEQ     2048
#define DMODEL  1024
#define NHEADS  16
#define HDIM    64
#define QKV_LD  3072
#define NTOK    (BATCH * SEQ)      // 4096
#define WINDOW  128
#define STRIDE  64

// Scratch (device globals: no allocation allowed)
__device__ float g_qkv[(size_t)NTOK * QKV_LD];   // 4096 x 3072
__device__ float g_y[(size_t)NTOK * DMODEL];     // 4096 x 1024

__device__ __forceinline__ unsigned f2tf(float f) {
    unsigned u;
    asm("cvt.rna.tf32.f32 %0, %1;" : "=r"(u) : "f"(f));
    return u;
}
__device__ __forceinline__ float4 cvt4(float4 v) {
    float4 t;
    t.x = __uint_as_float(f2tf(v.x));
    t.y = __uint_as_float(f2tf(v.y));
    t.z = __uint_as_float(f2tf(v.z));
    t.w = __uint_as_float(f2tf(v.w));
    return t;
}

// Fast exp2 on the FMA pipe (x <= 0; clamped at -126). Rel err < 1e-4.
__device__ __forceinline__ float fexp2(float x) {
    x = fmaxf(x, -126.0f);
    float n = floorf(x);
    float f = x - n;
    float p = 0.00133336f;
    p = fmaf(p, f, 0.00961813f);
    p = fmaf(p, f, 0.05550411f);
    p = fmaf(p, f, 0.24022651f);
    p = fmaf(p, f, 0.69314718f);
    p = fmaf(p, f, 1.0f);
    return __int_as_float(((int)n + 127) << 23) * p;
}

// ===========================================================================
// TF32 mma.sync GEMM (R5 config verbatim — best measured, 440us run):
// CTA 256x128, BK=16, 256 threads = 8 warps (4M x 2N), warp tile 64x64,
// double-buffered smem with register prefetch; cvt to tf32 during staging.
// ===========================================================================
#define BM 256
#define BN 128
#define BK 16
#define AP 20
#define BP 136
#define GEMM_SMEM ((2 * BM * AP + 2 * BK * BP) * (int)sizeof(float))  // 58368

__global__ __launch_bounds__(256, 1) void tgemm(
    const float* __restrict__ A, const float* __restrict__ B,
    float* __restrict__ C, int M, int N, int K)
{
    extern __shared__ float sm[];
    float* As0 = sm;                    // [2][BM*AP]  ([m][k])
    float* Bs0 = sm + 2 * BM * AP;      // [2][BK*BP]  ([k][n])

    const int tid  = threadIdx.x;
    const int lane = tid & 31;
    const int wid  = tid >> 5;
    const int warp_m = wid >> 1;
    const int warp_n = wid & 1;
    const int row0 = blockIdx.y * BM;
    const int col0 = blockIdx.x * BN;

    const int ar = tid >> 2;             // 0..63
    const int ak = (tid & 3) * 4;        // 0,4,8,12
    const int bk = tid >> 4;             // 0..15
    const int bn = (tid & 15) * 8;       // 0..120

    float acc[4][8][4];
#pragma unroll
    for (int mi = 0; mi < 4; ++mi)
#pragma unroll
        for (int ni = 0; ni < 8; ++ni)
#pragma unroll
            for (int e = 0; e < 4; ++e) acc[mi][ni][e] = 0.0f;

    const int nk = K / BK;

    float4 ra[4], rb[2];
#pragma unroll
    for (int p = 0; p < 4; ++p)
        ra[p] = *(const float4*)(A + (size_t)(row0 + p * 64 + ar) * K + ak);
    rb[0] = *(const float4*)(B + (size_t)bk * N + col0 + bn);
    rb[1] = *(const float4*)(B + (size_t)bk * N + col0 + bn + 4);
#pragma unroll
    for (int p = 0; p < 4; ++p)
        *(float4*)&As0[(p * 64 + ar) * AP + ak] = cvt4(ra[p]);
    *(float4*)&Bs0[bk * BP + bn]     = cvt4(rb[0]);
    *(float4*)&Bs0[bk * BP + bn + 4] = cvt4(rb[1]);
    __syncthreads();

    const int lrow = lane & 15;
    const int lk4  = (lane & 16) ? 4 : 0;
    const int bkr  = lane & 3;
    const int bnc  = warp_n * 64 + (lane >> 2);

    for (int it = 0; it < nk; ++it) {
        const int cur = it & 1;

        if (it + 1 < nk) {
            const int k0 = (it + 1) * BK;
#pragma unroll
            for (int p = 0; p < 4; ++p)
                ra[p] = *(const float4*)(A + (size_t)(row0 + p * 64 + ar) * K + k0 + ak);
            rb[0] = *(const float4*)(B + (size_t)(k0 + bk) * N + col0 + bn);
            rb[1] = *(const float4*)(B + (size_t)(k0 + bk) * N + col0 + bn + 4);
        }

        const float*   Ac  = As0 + cur * BM * AP;
        const float*   Bc  = Bs0 + cur * BK * BP;
        const unsigned smA = (unsigned)__cvta_generic_to_shared(Ac);
#pragma unroll
        for (int ks = 0; ks < 2; ++ks) {
            unsigned a[4][4];
#pragma unroll
            for (int mi = 0; mi < 4; ++mi) {
                unsigned ad = smA +
                    (((warp_m * 64 + mi * 16 + lrow) * AP + ks * 8 + lk4) << 2);
                asm volatile(
                    "ldmatrix.sync.aligned.m8n8.x4.shared.b16 {%0,%1,%2,%3}, [%4];"
                    : "=r"(a[mi][0]), "=r"(a[mi][1]), "=r"(a[mi][2]), "=r"(a[mi][3])
                    : "r"(ad));
            }
            unsigned b0[8], b1[8];
            const int krow = ks * 8 + bkr;
#pragma unroll
            for (int ni = 0; ni < 8; ++ni) {
                b0[ni] = __float_as_uint(Bc[krow * BP + bnc + ni * 8]);
                b1[ni] = __float_as_uint(Bc[(krow + 4) * BP + bnc + ni * 8]);
            }
#pragma unroll
            for (int mi = 0; mi < 4; ++mi)
#pragma unroll
                for (int ni = 0; ni < 8; ++ni) {
                    asm volatile(
                        "mma.sync.aligned.m16n8k8.row.col.f32.tf32.tf32.f32 "
                        "{%0,%1,%2,%3}, {%4,%5,%6,%7}, {%8,%9}, {%0,%1,%2,%3};"
                        : "+f"(acc[mi][ni][0]), "+f"(acc[mi][ni][1]),
                          "+f"(acc[mi][ni][2]), "+f"(acc[mi][ni][3])
                        : "r"(a[mi][0]), "r"(a[mi][1]), "r"(a[mi][2]), "r"(a[mi][3]),
                          "r"(b0[ni]), "r"(b1[ni]));
                }
        }

        if (it + 1 < nk) {
            float* An = As0 + (cur ^ 1) * BM * AP;
            float* Bn = Bs0 + (cur ^ 1) * BK * BP;
#pragma unroll
            for (int p = 0; p < 4; ++p)
                *(float4*)&An[(p * 64 + ar) * AP + ak] = cvt4(ra[p]);
            *(float4*)&Bn[bk * BP + bn]     = cvt4(rb[0]);
            *(float4*)&Bn[bk * BP + bn + 4] = cvt4(rb[1]);
        }
        __syncthreads();
    }

    const int g  = lane >> 2;
    const int tg = lane & 3;
#pragma unroll
    for (int mi = 0; mi < 4; ++mi) {
#pragma unroll
        for (int ni = 0; ni < 8; ++ni) {
            const int row = row0 + warp_m * 64 + mi * 16 + g;
            const int col = col0 + warp_n * 64 + ni * 8 + 2 * tg;
            *(float2*)&C[(size_t)row * N + col] =
                make_float2(acc[mi][ni][0], acc[mi][ni][1]);
            *(float2*)&C[(size_t)(row + 8) * N + col] =
                make_float2(acc[mi][ni][2], acc[mi][ni][3]);
        }
    }
}

// ===========================================================================
// Tensor-core sparse flash attention.
// Grid (S/64, H, B), 128 threads = 4 warps; warp w owns query rows 16w..16w+15.
// S = Q K^T and O += P V via m16n8k8 tf32 mma (fragment patterns identical to
// the validated tgemm). Q/K staged [row][d] pitch 68 (tf32-rounded); V staged
// transposed [d][key] pitch 68 (B-frag reads bank-distinct: (4n+k)%32).
// Online softmax on c-fragments; quad shuffles; exp on FMA pipe.
// ===========================================================================
#define P68 68
#define ATTN_SMEM (4 * 64 * P68 * (int)sizeof(float))   // 69632 B
#define SC2 0.18033688f   // (1/sqrt(64)) * log2(e)

__global__ __launch_bounds__(128) void sparse_attn(
    const float* __restrict__ qkv, float* __restrict__ y)
{
    extern __shared__ float smf[];
    float* Qt = smf;                 // [64 q][P68]   (tf32 bits)
    float* Ks = Qt + 64 * P68;       // [64 key][P68] (tf32 bits)
    float* Vt = Ks + 64 * P68;       // [64 d][P68]   (tf32 bits, transposed)
    float* Ps = Vt + 64 * P68;       // [64 q][P68]   (tf32 bits)

    const int t    = blockIdx.x;
    const int h    = blockIdx.y;
    const int b    = blockIdx.z;
    const int tid  = threadIdx.x;
    const int lane = tid & 31;
    const int w    = tid >> 5;       // 0..3
    const int r0   = t * 64;

    const size_t base = (size_t)b * SEQ * QKV_LD;

    // ---- stage Q (tf32-rounded) ----
    for (int e = tid; e < 1024; e += 128) {
        const int tok = e >> 4;
        const int d4  = (e & 15) * 4;
        float4 v = cvt4(*(const float4*)(qkv + base + (size_t)(r0 + tok) * QKV_LD + h * HDIM + d4));
        *(float4*)&Qt[tok * P68 + d4] = v;
    }

    const int g  = lane >> 2;        // 0..7
    const int tg = lane & 3;         // 0..3
    const int lrow = lane & 15;
    const int lk4  = (lane & 16) ? 4 : 0;

    float m0 = -3.0e38f, m1 = -3.0e38f, l0 = 0.0f, l1 = 0.0f;
    float o[8][4];
#pragma unroll
    for (int ni = 0; ni < 8; ++ni)
#pragma unroll
        for (int e = 0; e < 4; ++e) o[ni][e] = 0.0f;

    const int kb_start = (t >= 2) ? (t - 2) : 0;
    const int n_win    = t - kb_start + 1;
    const int nglob    = (t >= 3) ? (t - 2) : 0;
    const int n_tiles  = n_win + (nglob > 0 ? 1 : 0);

    const unsigned smQ = (unsigned)__cvta_generic_to_shared(Qt);
    const unsigned smP = (unsigned)__cvta_generic_to_shared(Ps);

    for (int it = 0; it < n_tiles; ++it) {
        const bool is_glob = (it == n_win);
        const int  kcol0   = (kb_start + it) * 64;

        __syncthreads();   // prior tile's mma reads of Ks/Vt done (also covers Q on it=0)

        // ---- stage K [key][d] and V transposed [d][key] ----
        for (int e = tid; e < 1024; e += 128) {
            const int tok = e >> 4;
            const int d4  = (e & 15) * 4;
            int key;
            bool valid;
            if (is_glob) { key = tok * STRIDE; valid = (tok < nglob); }
            else         { key = kcol0 + tok;  valid = true; }
            float4 kv, vv;
            if (valid) {
                const float* kp = qkv + base + (size_t)key * QKV_LD + DMODEL + h * HDIM + d4;
                kv = cvt4(*(const float4*)kp);
                vv = cvt4(*(const float4*)(kp + DMODEL));
            } else {
                kv = make_float4(0.f, 0.f, 0.f, 0.f);
                vv = kv;
            }
            *(float4*)&Ks[tok * P68 + d4] = kv;
            Vt[(d4 + 0) * P68 + tok] = vv.x;
            Vt[(d4 + 1) * P68 + tok] = vv.y;
            Vt[(d4 + 2) * P68 + tok] = vv.z;
            Vt[(d4 + 3) * P68 + tok] = vv.w;
        }
        __syncthreads();

        // ---- S = Q K^T (tensor) ----
        float s[8][4];
#pragma unroll
        for (int ni = 0; ni < 8; ++ni)
#pragma unroll
            for (int e = 0; e < 4; ++e) s[ni][e] = 0.0f;

#pragma unroll
        for (int ks = 0; ks < 8; ++ks) {
            unsigned a[4];
            unsigned ad = smQ + (((w * 16 + lrow) * P68 + ks * 8 + lk4) << 2);
            asm volatile(
                "ldmatrix.sync.aligned.m8n8.x4.shared.b16 {%0,%1,%2,%3}, [%4];"
                : "=r"(a[0]), "=r"(a[1]), "=r"(a[2]), "=r"(a[3]) : "r"(ad));
            const int kk = ks * 8 + tg;
#pragma unroll
            for (int ni = 0; ni < 8; ++ni) {
                unsigned b0 = __float_as_uint(Ks[(ni * 8 + g) * P68 + kk]);
                unsigned b1 = __float_as_uint(Ks[(ni * 8 + g) * P68 + kk + 4]);
                asm volatile(
                    "mma.sync.aligned.m16n8k8.row.col.f32.tf32.tf32.f32 "
                    "{%0,%1,%2,%3}, {%4,%5,%6,%7}, {%8,%9}, {%0,%1,%2,%3};"
                    : "+f"(s[ni][0]), "+f"(s[ni][1]), "+f"(s[ni][2]), "+f"(s[ni][3])
                    : "r"(a[0]), "r"(a[1]), "r"(a[2]), "r"(a[3]), "r"(b0), "r"(b1));
            }
        }

        // ---- mask + scale (base-2 domain) ----
        const int row_lo = r0 + w * 16 + g;
        const int row_hi = row_lo + 8;
#pragma unroll
        for (int ni = 0; ni < 8; ++ni) {
            const int col0 = ni * 8 + 2 * tg;
#pragma unroll
            for (int e = 0; e < 4; ++e) {
                const int col = col0 + (e & 1);
                const int row = (e < 2) ? row_lo : row_hi;
                bool ok;
                if (is_glob) {
                    ok = col < nglob;
                } else {
                    const int c = kcol0 + col;
                    ok = (c <= row) && ((row - c) <= (WINDOW - 1) || (c & (STRIDE - 1)) == 0);
                }
                s[ni][e] = ok ? s[ni][e] * SC2 : -3.0e38f;
            }
        }

        // ---- online softmax on fragments ----
        float mx0 = -3.0e38f, mx1 = -3.0e38f;
#pragma unroll
        for (int ni = 0; ni < 8; ++ni) {
            mx0 = fmaxf(mx0, fmaxf(s[ni][0], s[ni][1]));
            mx1 = fmaxf(mx1, fmaxf(s[ni][2], s[ni][3]));
        }
        mx0 = fmaxf(mx0, __shfl_xor_sync(0xffffffffu, mx0, 1));
        mx0 = fmaxf(mx0, __shfl_xor_sync(0xffffffffu, mx0, 2));
        mx1 = fmaxf(mx1, __shfl_xor_sync(0xffffffffu, mx1, 1));
        mx1 = fmaxf(mx1, __shfl_xor_sync(0xffffffffu, mx1, 2));

        const float mn0 = fmaxf(m0, mx0);
        const float mn1 = fmaxf(m1, mx1);
        const float al0 = fexp2(m0 - mn0);
        const float al1 = fexp2(m1 - mn1);

        float rs0 = 0.0f, rs1 = 0.0f;
#pragma unroll
        for (int ni = 0; ni < 8; ++ni) {
            const int col0 = ni * 8 + 2 * tg;
            float p0 = fexp2(s[ni][0] - mn0);
            float p1 = fexp2(s[ni][1] - mn0);
            float p2 = fexp2(s[ni][2] - mn1);
            float p3 = fexp2(s[ni][3] - mn1);
            rs0 += p0 + p1;
            rs1 += p2 + p3;
            float2 lo, hi;
            lo.x = __uint_as_float(f2tf(p0));
            lo.y = __uint_as_float(f2tf(p1));
            hi.x = __uint_as_float(f2tf(p2));
            hi.y = __uint_as_float(f2tf(p3));
            *(float2*)&Ps[(w * 16 + g) * P68 + col0]     = lo;
            *(float2*)&Ps[(w * 16 + g + 8) * P68 + col0] = hi;
        }
        rs0 += __shfl_xor_sync(0xffffffffu, rs0, 1);
        rs0 += __shfl_xor_sync(0xffffffffu, rs0, 2);
        rs1 += __shfl_xor_sync(0xffffffffu, rs1, 1);
        rs1 += __shfl_xor_sync(0xffffffffu, rs1, 2);

        l0 = l0 * al0 + rs0;
        l1 = l1 * al1 + rs1;
        m0 = mn0;
        m1 = mn1;
#pragma unroll
        for (int ni = 0; ni < 8; ++ni) {
            o[ni][0] *= al0;
            o[ni][1] *= al0;
            o[ni][2] *= al1;
            o[ni][3] *= al1;
        }
        __syncwarp();

        // ---- O += P V (tensor) ----
#pragma unroll
        for (int ks = 0; ks < 8; ++ks) {
            unsigned a[4];
            unsigned ad = smP + (((w * 16 + lrow) * P68 + ks * 8 + lk4) << 2);
            asm volatile(
                "ldmatrix.sync.aligned.m8n8.x4.shared.b16 {%0,%1,%2,%3}, [%4];"
                : "=r"(a[0]), "=r"(a[1]), "=r"(a[2]), "=r"(a[3]) : "r"(ad));
            const int kk = ks * 8 + tg;
#pragma unroll
            for (int ni = 0; ni < 8; ++ni) {
                unsigned b0 = __float_as_uint(Vt[(ni * 8 + g) * P68 + kk]);
                unsigned b1 = __float_as_uint(Vt[(ni * 8 + g) * P68 + kk + 4]);
                asm volatile(
                    "mma.sync.aligned.m16n8k8.row.col.f32.tf32.tf32.f32 "
                    "{%0,%1,%2,%3}, {%4,%5,%6,%7}, {%8,%9}, {%0,%1,%2,%3};"
                    : "+f"(o[ni][0]), "+f"(o[ni][1]), "+f"(o[ni][2]), "+f"(o[ni][3])
                    : "r"(a[0]), "r"(a[1]), "r"(a[2]), "r"(a[3]), "r"(b0), "r"(b1));
            }
        }
        __syncwarp();
    }

    // ---- epilogue: normalize + write y ----
    const float inv0 = 1.0f / l0;
    const float inv1 = 1.0f / l1;
    const size_t row_lo = (size_t)b * SEQ + r0 + w * 16 + g;
#pragma unroll
    for (int ni = 0; ni < 8; ++ni) {
        const int col = h * HDIM + ni * 8 + 2 * tg;
        *(float2*)&y[row_lo * DMODEL + col] =
            make_float2(o[ni][0] * inv0, o[ni][1] * inv0);
        *(float2*)&y[(row_lo + 8) * DMODEL + col] =
            make_float2(o[ni][2] * inv1, o[ni][3] * inv1);
    }
}

// ---------------------------------------------------------------------------
extern "C" void kernel_launch(void* const* d_in, const int* in_sizes, int n_in,
                              void* d_out, int out_size)
{
    const float* x     = (const float*)d_in[0];
    const float* Wqkv  = (const float*)d_in[1];
    const float* Wproj = (const float*)d_in[2];
    float* out = (float*)d_out;

    float *qkv = nullptr, *y = nullptr;
    cudaGetSymbolAddress((void**)&qkv, g_qkv);
    cudaGetSymbolAddress((void**)&y, g_y);

    cudaFuncSetAttribute(tgemm, cudaFuncAttributeMaxDynamicSharedMemorySize, GEMM_SMEM);
    cudaFuncSetAttribute(sparse_attn, cudaFuncAttributeMaxDynamicSharedMemorySize, ATTN_SMEM);

    // 1) QKV projection: [4096,1024] @ [1024,3072]
    tgemm<<<dim3(QKV_LD / BN, NTOK / BM), 256, GEMM_SMEM>>>(x, Wqkv, qkv, NTOK, QKV_LD, DMODEL);

    // 2) Sparse attention (tensor cores)
    sparse_attn<<<dim3(SEQ / 64, NHEADS, BATCH), 128, ATTN_SMEM>>>(qkv, y);

    // 3) Output projection: [4096,1024] @ [1024,1024]
    tgemm<<<dim3(DMODEL / BN, NTOK / BM), 256, GEMM_SMEM>>>(y, Wproj, out, NTOK, DMODEL, DMODEL);
}

// round 12
// speedup vs baseline: 1.3819x; 1.0192x over previous
#include <cuda_runtime.h>
#include <cuda_fp16.h>
#include <cstdint>
#include <cfloat>

// Problem constants
#define BATCH   2
#define SEQ     2048
#define DMODEL  1024
#define NHEADS  16
#define HDIM    64
#define QKV_LD  3072
#define NTOK    (BATCH * SEQ)      // 4096
#define WINDOW  128
#define STRIDE  64

// Scratch (device globals: no allocation allowed)
__device__ float g_qkv[(size_t)NTOK * QKV_LD];   // 4096 x 3072
__device__ float g_y[(size_t)NTOK * DMODEL];     // 4096 x 1024

__device__ __forceinline__ unsigned f2tf(float f) {
    unsigned u;
    asm("cvt.rna.tf32.f32 %0, %1;" : "=r"(u) : "f"(f));
    return u;
}
__device__ __forceinline__ float4 cvt4(float4 v) {
    float4 t;
    t.x = __uint_as_float(f2tf(v.x));
    t.y = __uint_as_float(f2tf(v.y));
    t.z = __uint_as_float(f2tf(v.z));
    t.w = __uint_as_float(f2tf(v.w));
    return t;
}
// pack two floats into half2 bits (x -> low, y -> high)
__device__ __forceinline__ unsigned f2h2(float x, float y) {
    __half2 h = __float22half2_rn(make_float2(x, y));
    return *reinterpret_cast<unsigned*>(&h);
}
// Fast exp2 on the FMA pipe (x <= 0; clamped at -126). Rel err < 1e-4.
__device__ __forceinline__ float fexp2(float x) {
    x = fmaxf(x, -126.0f);
    float n = floorf(x);
    float f = x - n;
    float p = 0.00133336f;
    p = fmaf(p, f, 0.00961813f);
    p = fmaf(p, f, 0.05550411f);
    p = fmaf(p, f, 0.24022651f);
    p = fmaf(p, f, 0.69314718f);
    p = fmaf(p, f, 1.0f);
    return __int_as_float(((int)n + 127) << 23) * p;
}

// ===========================================================================
// FP16 mma.sync GEMM (m16n8k16, fp32 accum): C[M,N] = A[M,K] @ B[K,N].
// CTA 256x128, BK=32, 256 threads = 8 warps (4M x 2N), warp tile 64x64.
// A staged [m][k] halves pitch 40; B staged [k][n] halves pitch 136.
// A frags: ldmatrix.x4; B frags: ldmatrix.x4.trans with lanes 16-31 at n+8
// (each x4.trans covers k16 x n16; 4 per ks cover the n64 warp tile).
// fp32->fp16 conversion folded into register staging. Double-buffered smem.
// ===========================================================================
#define BM 256
#define BN 128
#define BKH 32
#define APH 40    // A pitch (halves): 80B row stride (conflict-free ldmatrix)
#define BPH 136   // B pitch (halves): 272B row stride (conflict-free ldmatrix)
#define GEMM_SMEM ((2 * (BM * APH + BKH * BPH)) * (int)sizeof(__half))  // 58368

__global__ __launch_bounds__(256, 1) void hgemm(
    const float* __restrict__ A, const float* __restrict__ B,
    float* __restrict__ C, int M, int N, int K)
{
    extern __shared__ __half smh[];
    __half* As0 = smh;                      // [2][BM*APH]  ([m][k])
    __half* Bs0 = smh + 2 * BM * APH;       // [2][BKH*BPH] ([k][n])

    const int tid  = threadIdx.x;
    const int lane = tid & 31;
    const int wid  = tid >> 5;
    const int warp_m = wid >> 1;            // 0..3
    const int warp_n = wid & 1;             // 0..1
    const int row0 = blockIdx.y * BM;
    const int col0 = blockIdx.x * BN;

    const int brow = tid >> 3;              // 0..31
    const int bn   = (tid & 7) * 16;        // 0..112 (halves)

    float acc[4][8][4];
#pragma unroll
    for (int mi = 0; mi < 4; ++mi)
#pragma unroll
        for (int ni = 0; ni < 8; ++ni)
#pragma unroll
            for (int e = 0; e < 4; ++e) acc[mi][ni][e] = 0.0f;

    const int nk = K / BKH;

    float4 ra[8], rb[4];
#pragma unroll
    for (int j = 0; j < 8; ++j)
        ra[j] = *(const float4*)(A + (size_t)(row0 + tid) * K + 4 * j);
#pragma unroll
    for (int j = 0; j < 4; ++j)
        rb[j] = *(const float4*)(B + (size_t)brow * N + col0 + bn + 4 * j);
    {
        uint4* ad = (uint4*)&As0[tid * APH];
#pragma unroll
        for (int q = 0; q < 4; ++q)
            ad[q] = make_uint4(f2h2(ra[2*q].x, ra[2*q].y), f2h2(ra[2*q].z, ra[2*q].w),
                               f2h2(ra[2*q+1].x, ra[2*q+1].y), f2h2(ra[2*q+1].z, ra[2*q+1].w));
        uint4* bd = (uint4*)&Bs0[brow * BPH + bn];
#pragma unroll
        for (int q = 0; q < 2; ++q)
            bd[q] = make_uint4(f2h2(rb[2*q].x, rb[2*q].y), f2h2(rb[2*q].z, rb[2*q].w),
                               f2h2(rb[2*q+1].x, rb[2*q+1].y), f2h2(rb[2*q+1].z, rb[2*q+1].w));
    }
    __syncthreads();

    const int lrow = lane & 15;
    const int lk8  = (lane & 16) ? 8 : 0;   // A: hi lanes read k+8
    const int ln8  = (lane & 16) >> 1;      // B: hi lanes read n+8

    for (int it = 0; it < nk; ++it) {
        const int cur = it & 1;

        if (it + 1 < nk) {
            const int k0 = (it + 1) * BKH;
#pragma unroll
            for (int j = 0; j < 8; ++j)
                ra[j] = *(const float4*)(A + (size_t)(row0 + tid) * K + k0 + 4 * j);
#pragma unroll
            for (int j = 0; j < 4; ++j)
                rb[j] = *(const float4*)(B + (size_t)(k0 + brow) * N + col0 + bn + 4 * j);
        }

        const __half* Ac = As0 + cur * BM * APH;
        const __half* Bc = Bs0 + cur * BKH * BPH;
        const unsigned smA = (unsigned)__cvta_generic_to_shared(Ac);
        const unsigned smB = (unsigned)__cvta_generic_to_shared(Bc);
#pragma unroll
        for (int ks = 0; ks < 2; ++ks) {
            unsigned a[4][4];
#pragma unroll
            for (int mi = 0; mi < 4; ++mi) {
                unsigned ad = smA +
                    (((warp_m * 64 + mi * 16 + lrow) * APH + ks * 16 + lk8) << 1);
                asm volatile(
                    "ldmatrix.sync.aligned.m8n8.x4.shared.b16 {%0,%1,%2,%3}, [%4];"
                    : "=r"(a[mi][0]), "=r"(a[mi][1]), "=r"(a[mi][2]), "=r"(a[mi][3])
                    : "r"(ad));
            }
            // B: 4 x ldmatrix.x4.trans, group ng covers n16 at warp_n*64+ng*16
            unsigned bf[4][4];
#pragma unroll
            for (int ng = 0; ng < 4; ++ng) {
                unsigned bd = smB +
                    (((ks * 16 + lrow) * BPH + warp_n * 64 + ng * 16 + ln8) << 1);
                asm volatile(
                    "ldmatrix.sync.aligned.m8n8.x4.trans.shared.b16 {%0,%1,%2,%3}, [%4];"
                    : "=r"(bf[ng][0]), "=r"(bf[ng][1]), "=r"(bf[ng][2]), "=r"(bf[ng][3])
                    : "r"(bd));
            }
#pragma unroll
            for (int mi = 0; mi < 4; ++mi)
#pragma unroll
                for (int ni = 0; ni < 8; ++ni) {
                    // n8 block ni at col warp_n*64 + ni*8:
                    // group ni>>1, regs {0,1} (ni even) or {2,3} (ni odd)
                    const unsigned b0 = bf[ni >> 1][(ni & 1) * 2];
                    const unsigned b1 = bf[ni >> 1][(ni & 1) * 2 + 1];
                    asm volatile(
                        "mma.sync.aligned.m16n8k16.row.col.f32.f16.f16.f32 "
                        "{%0,%1,%2,%3}, {%4,%5,%6,%7}, {%8,%9}, {%0,%1,%2,%3};"
                        : "+f"(acc[mi][ni][0]), "+f"(acc[mi][ni][1]),
                          "+f"(acc[mi][ni][2]), "+f"(acc[mi][ni][3])
                        : "r"(a[mi][0]), "r"(a[mi][1]), "r"(a[mi][2]), "r"(a[mi][3]),
                          "r"(b0), "r"(b1));
                }
        }

        if (it + 1 < nk) {
            __half* An = As0 + (cur ^ 1) * BM * APH;
            __half* Bn = Bs0 + (cur ^ 1) * BKH * BPH;
            uint4* ad = (uint4*)&An[tid * APH];
#pragma unroll
            for (int q = 0; q < 4; ++q)
                ad[q] = make_uint4(f2h2(ra[2*q].x, ra[2*q].y), f2h2(ra[2*q].z, ra[2*q].w),
                                   f2h2(ra[2*q+1].x, ra[2*q+1].y), f2h2(ra[2*q+1].z, ra[2*q+1].w));
            uint4* bd = (uint4*)&Bn[brow * BPH + bn];
#pragma unroll
            for (int q = 0; q < 2; ++q)
                bd[q] = make_uint4(f2h2(rb[2*q].x, rb[2*q].y), f2h2(rb[2*q].z, rb[2*q].w),
                                   f2h2(rb[2*q+1].x, rb[2*q+1].y), f2h2(rb[2*q+1].z, rb[2*q+1].w));
        }
        __syncthreads();
    }

    // ---- epilogue: c-fragment layout (m16n8): rows g, g+8; cols ni*8 + 2tg ----
    const int g  = lane >> 2;
    const int tg = lane & 3;
#pragma unroll
    for (int mi = 0; mi < 4; ++mi) {
#pragma unroll
        for (int ni = 0; ni < 8; ++ni) {
            const int row = row0 + warp_m * 64 + mi * 16 + g;
            const int col = col0 + warp_n * 64 + ni * 8 + 2 * tg;
            *(float2*)&C[(size_t)row * N + col] =
                make_float2(acc[mi][ni][0], acc[mi][ni][1]);
            *(float2*)&C[(size_t)(row + 8) * N + col] =
                make_float2(acc[mi][ni][2], acc[mi][ni][3]);
        }
    }
}

// ===========================================================================
// Tensor-core sparse flash attention (unchanged from R10 — validated).
// ===========================================================================
#define P68 68
#define ATTN_SMEM (4 * 64 * P68 * (int)sizeof(float))   // 69632 B
#define SC2 0.18033688f   // (1/sqrt(64)) * log2(e)

__global__ __launch_bounds__(128) void sparse_attn(
    const float* __restrict__ qkv, float* __restrict__ y)
{
    extern __shared__ float smf[];
    float* Qt = smf;                 // [64 q][P68]
    float* Ks = Qt + 64 * P68;       // [64 key][P68]
    float* Vt = Ks + 64 * P68;       // [64 d][P68] transposed
    float* Ps = Vt + 64 * P68;       // [64 q][P68]

    const int t    = blockIdx.x;
    const int h    = blockIdx.y;
    const int b    = blockIdx.z;
    const int tid  = threadIdx.x;
    const int lane = tid & 31;
    const int w    = tid >> 5;
    const int r0   = t * 64;

    const size_t base = (size_t)b * SEQ * QKV_LD;

    for (int e = tid; e < 1024; e += 128) {
        const int tok = e >> 4;
        const int d4  = (e & 15) * 4;
        float4 v = cvt4(*(const float4*)(qkv + base + (size_t)(r0 + tok) * QKV_LD + h * HDIM + d4));
        *(float4*)&Qt[tok * P68 + d4] = v;
    }

    const int g  = lane >> 2;
    const int tg = lane & 3;
    const int lrow = lane & 15;
    const int lk4  = (lane & 16) ? 4 : 0;

    float m0 = -3.0e38f, m1 = -3.0e38f, l0 = 0.0f, l1 = 0.0f;
    float o[8][4];
#pragma unroll
    for (int ni = 0; ni < 8; ++ni)
#pragma unroll
        for (int e = 0; e < 4; ++e) o[ni][e] = 0.0f;

    const int kb_start = (t >= 2) ? (t - 2) : 0;
    const int n_win    = t - kb_start + 1;
    const int nglob    = (t >= 3) ? (t - 2) : 0;
    const int n_tiles  = n_win + (nglob > 0 ? 1 : 0);

    const unsigned smQ = (unsigned)__cvta_generic_to_shared(Qt);
    const unsigned smP = (unsigned)__cvta_generic_to_shared(Ps);

    for (int it = 0; it < n_tiles; ++it) {
        const bool is_glob = (it == n_win);
        const int  kcol0   = (kb_start + it) * 64;

        __syncthreads();

        for (int e = tid; e < 1024; e += 128) {
            const int tok = e >> 4;
            const int d4  = (e & 15) * 4;
            int key;
            bool valid;
            if (is_glob) { key = tok * STRIDE; valid = (tok < nglob); }
            else         { key = kcol0 + tok;  valid = true; }
            float4 kv, vv;
            if (valid) {
                const float* kp = qkv + base + (size_t)key * QKV_LD + DMODEL + h * HDIM + d4;
                kv = cvt4(*(const float4*)kp);
                vv = cvt4(*(const float4*)(kp + DMODEL));
            } else {
                kv = make_float4(0.f, 0.f, 0.f, 0.f);
                vv = kv;
            }
            *(float4*)&Ks[tok * P68 + d4] = kv;
            Vt[(d4 + 0) * P68 + tok] = vv.x;
            Vt[(d4 + 1) * P68 + tok] = vv.y;
            Vt[(d4 + 2) * P68 + tok] = vv.z;
            Vt[(d4 + 3) * P68 + tok] = vv.w;
        }
        __syncthreads();

        float s[8][4];
#pragma unroll
        for (int ni = 0; ni < 8; ++ni)
#pragma unroll
            for (int e = 0; e < 4; ++e) s[ni][e] = 0.0f;

#pragma unroll
        for (int ks = 0; ks < 8; ++ks) {
            unsigned a[4];
            unsigned ad = smQ + (((w * 16 + lrow) * P68 + ks * 8 + lk4) << 2);
            asm volatile(
                "ldmatrix.sync.aligned.m8n8.x4.shared.b16 {%0,%1,%2,%3}, [%4];"
                : "=r"(a[0]), "=r"(a[1]), "=r"(a[2]), "=r"(a[3]) : "r"(ad));
            const int kk = ks * 8 + tg;
#pragma unroll
            for (int ni = 0; ni < 8; ++ni) {
                unsigned b0 = __float_as_uint(Ks[(ni * 8 + g) * P68 + kk]);
                unsigned b1 = __float_as_uint(Ks[(ni * 8 + g) * P68 + kk + 4]);
                asm volatile(
                    "mma.sync.aligned.m16n8k8.row.col.f32.tf32.tf32.f32 "
                    "{%0,%1,%2,%3}, {%4,%5,%6,%7}, {%8,%9}, {%0,%1,%2,%3};"
                    : "+f"(s[ni][0]), "+f"(s[ni][1]), "+f"(s[ni][2]), "+f"(s[ni][3])
                    : "r"(a[0]), "r"(a[1]), "r"(a[2]), "r"(a[3]), "r"(b0), "r"(b1));
            }
        }

        const int row_lo = r0 + w * 16 + g;
        const int row_hi = row_lo + 8;
#pragma unroll
        for (int ni = 0; ni < 8; ++ni) {
            const int col0 = ni * 8 + 2 * tg;
#pragma unroll
            for (int e = 0; e < 4; ++e) {
                const int col = col0 + (e & 1);
                const int row = (e < 2) ? row_lo : row_hi;
                bool ok;
                if (is_glob) {
                    ok = col < nglob;
                } else {
                    const int c = kcol0 + col;
                    ok = (c <= row) && ((row - c) <= (WINDOW - 1) || (c & (STRIDE - 1)) == 0);
                }
                s[ni][e] = ok ? s[ni][e] * SC2 : -3.0e38f;
            }
        }

        float mx0 = -3.0e38f, mx1 = -3.0e38f;
#pragma unroll
        for (int ni = 0; ni < 8; ++ni) {
            mx0 = fmaxf(mx0, fmaxf(s[ni][0], s[ni][1]));
            mx1 = fmaxf(mx1, fmaxf(s[ni][2], s[ni][3]));
        }
        mx0 = fmaxf(mx0, __shfl_xor_sync(0xffffffffu, mx0, 1));
        mx0 = fmaxf(mx0, __shfl_xor_sync(0xffffffffu, mx0, 2));
        mx1 = fmaxf(mx1, __shfl_xor_sync(0xffffffffu, mx1, 1));
        mx1 = fmaxf(mx1, __shfl_xor_sync(0xffffffffu, mx1, 2));

        const float mn0 = fmaxf(m0, mx0);
        const float mn1 = fmaxf(m1, mx1);
        const float al0 = fexp2(m0 - mn0);
        const float al1 = fexp2(m1 - mn1);

        float rs0 = 0.0f, rs1 = 0.0f;
#pragma unroll
        for (int ni = 0; ni < 8; ++ni) {
            const int col0 = ni * 8 + 2 * tg;
            float p0 = fexp2(s[ni][0] - mn0);
            float p1 = fexp2(s[ni][1] - mn0);
            float p2 = fexp2(s[ni][2] - mn1);
            float p3 = fexp2(s[ni][3] - mn1);
            rs0 += p0 + p1;
            rs1 += p2 + p3;
            float2 lo, hi;
            lo.x = __uint_as_float(f2tf(p0));
            lo.y = __uint_as_float(f2tf(p1));
            hi.x = __uint_as_float(f2tf(p2));
            hi.y = __uint_as_float(f2tf(p3));
            *(float2*)&Ps[(w * 16 + g) * P68 + col0]     = lo;
            *(float2*)&Ps[(w * 16 + g + 8) * P68 + col0] = hi;
        }
        rs0 += __shfl_xor_sync(0xffffffffu, rs0, 1);
        rs0 += __shfl_xor_sync(0xffffffffu, rs0, 2);
        rs1 += __shfl_xor_sync(0xffffffffu, rs1, 1);
        rs1 += __shfl_xor_sync(0xffffffffu, rs1, 2);

        l0 = l0 * al0 + rs0;
        l1 = l1 * al1 + rs1;
        m0 = mn0;
        m1 = mn1;
#pragma unroll
        for (int ni = 0; ni < 8; ++ni) {
            o[ni][0] *= al0;
            o[ni][1] *= al0;
            o[ni][2] *= al1;
            o[ni][3] *= al1;
        }
        __syncwarp();

#pragma unroll
        for (int ks = 0; ks < 8; ++ks) {
            unsigned a[4];
            unsigned ad = smP + (((w * 16 + lrow) * P68 + ks * 8 + lk4) << 2);
            asm volatile(
                "ldmatrix.sync.aligned.m8n8.x4.shared.b16 {%0,%1,%2,%3}, [%4];"
                : "=r"(a[0]), "=r"(a[1]), "=r"(a[2]), "=r"(a[3]) : "r"(ad));
            const int kk = ks * 8 + tg;
#pragma unroll
            for (int ni = 0; ni < 8; ++ni) {
                unsigned b0 = __float_as_uint(Vt[(ni * 8 + g) * P68 + kk]);
                unsigned b1 = __float_as_uint(Vt[(ni * 8 + g) * P68 + kk + 4]);
                asm volatile(
                    "mma.sync.aligned.m16n8k8.row.col.f32.tf32.tf32.f32 "
                    "{%0,%1,%2,%3}, {%4,%5,%6,%7}, {%8,%9}, {%0,%1,%2,%3};"
                    : "+f"(o[ni][0]), "+f"(o[ni][1]), "+f"(o[ni][2]), "+f"(o[ni][3])
                    : "r"(a[0]), "r"(a[1]), "r"(a[2]), "r"(a[3]), "r"(b0), "r"(b1));
            }
        }
        __syncwarp();
    }

    const float inv0 = 1.0f / l0;
    const float inv1 = 1.0f / l1;
    const size_t row_lo = (size_t)b * SEQ + r0 + w * 16 + g;
#pragma unroll
    for (int ni = 0; ni < 8; ++ni) {
        const int col = h * HDIM + ni * 8 + 2 * tg;
        *(float2*)&y[row_lo * DMODEL + col] =
            make_float2(o[ni][0] * inv0, o[ni][1] * inv0);
        *(float2*)&y[(row_lo + 8) * DMODEL + col] =
            make_float2(o[ni][2] * inv1, o[ni][3] * inv1);
    }
}

// ---------------------------------------------------------------------------
extern "C" void kernel_launch(void* const* d_in, const int* in_sizes, int n_in,
                              void* d_out, int out_size)
{
    const float* x     = (const float*)d_in[0];
    const float* Wqkv  = (const float*)d_in[1];
    const float* Wproj = (const float*)d_in[2];
    float* out = (float*)d_out;

    float *qkv = nullptr, *y = nullptr;
    cudaGetSymbolAddress((void**)&qkv, g_qkv);
    cudaGetSymbolAddress((void**)&y, g_y);

    cudaFuncSetAttribute(hgemm, cudaFuncAttributeMaxDynamicSharedMemorySize, GEMM_SMEM);
    cudaFuncSetAttribute(sparse_attn, cudaFuncAttributeMaxDynamicSharedMemorySize, ATTN_SMEM);

    // 1) QKV projection: [4096,1024] @ [1024,3072]  (fp16 mma, fp32 accum)
    hgemm<<<dim3(QKV_LD / BN, NTOK / BM), 256, GEMM_SMEM>>>(x, Wqkv, qkv, NTOK, QKV_LD, DMODEL);

    // 2) Sparse attention (tf32 tensor cores)
    sparse_attn<<<dim3(SEQ / 64, NHEADS, BATCH), 128, ATTN_SMEM>>>(qkv, y);

    // 3) Output projection: [4096,1024] @ [1024,1024]  (fp16 mma, fp32 accum)
    hgemm<<<dim3(DMODEL / BN, NTOK / BM), 256, GEMM_SMEM>>>(y, Wproj, out, NTOK, DMODEL, DMODEL);
}

// round 13
// speedup vs baseline: 2.1668x; 1.5680x over previous
#include <cuda_runtime.h>
#include <cuda_fp16.h>
#include <cstdint>
#include <cfloat>

// Problem constants
#define BATCH   2
#define SEQ     2048
#define DMODEL  1024
#define NHEADS  16
#define HDIM    64
#define QKV_LD  3072
#define NTOK    (BATCH * SEQ)      // 4096
#define WINDOW  128
#define STRIDE  64

// Scratch (device globals: no allocation allowed)
__device__ float g_qkv[(size_t)NTOK * QKV_LD];   // 4096 x 3072
__device__ float g_y[(size_t)NTOK * DMODEL];     // 4096 x 1024

__device__ __forceinline__ unsigned f2tf(float f) {
    unsigned u;
    asm("cvt.rna.tf32.f32 %0, %1;" : "=r"(u) : "f"(f));
    return u;
}
__device__ __forceinline__ float4 cvt4(float4 v) {
    float4 t;
    t.x = __uint_as_float(f2tf(v.x));
    t.y = __uint_as_float(f2tf(v.y));
    t.z = __uint_as_float(f2tf(v.z));
    t.w = __uint_as_float(f2tf(v.w));
    return t;
}
// pack two floats into half2 bits (x -> low, y -> high)
__device__ __forceinline__ unsigned f2h2(float x, float y) {
    __half2 h = __float22half2_rn(make_float2(x, y));
    return *reinterpret_cast<unsigned*>(&h);
}
__device__ __forceinline__ uint2 h4(float4 v) {
    return make_uint2(f2h2(v.x, v.y), f2h2(v.z, v.w));
}
// Fast exp2 on the FMA pipe (x <= 0; clamped at -126). Rel err < 1e-4.
__device__ __forceinline__ float fexp2(float x) {
    x = fmaxf(x, -126.0f);
    float n = floorf(x);
    float f = x - n;
    float p = 0.00133336f;
    p = fmaf(p, f, 0.00961813f);
    p = fmaf(p, f, 0.05550411f);
    p = fmaf(p, f, 0.24022651f);
    p = fmaf(p, f, 0.69314718f);
    p = fmaf(p, f, 1.0f);
    return __int_as_float(((int)n + 127) << 23) * p;
}

// ===========================================================================
// FP16 mma.sync GEMM (m16n8k16, fp32 accum): C[M,N] = A[M,K] @ B[K,N].
// CTA 256x128, BK=32, 256 threads = 8 warps (4M x 2N), warp tile 64x64.
// COALESCED loaders (R13 fix): A 8 lanes/row -> nL=4 per LDG;
// B 32 lanes/row -> nL=4 per LDG. fp32->fp16 in registers during staging.
// A staged [m][k] halves pitch 40; B staged [k][n] halves pitch 136.
// ===========================================================================
#define BM 256
#define BN 128
#define BKH 32
#define APH 40    // A pitch (halves): 80B row stride
#define BPH 136   // B pitch (halves): 272B row stride
#define GEMM_SMEM ((2 * (BM * APH + BKH * BPH)) * (int)sizeof(__half))  // 58368

__global__ __launch_bounds__(256, 1) void hgemm(
    const float* __restrict__ A, const float* __restrict__ B,
    float* __restrict__ C, int M, int N, int K)
{
    extern __shared__ __half smh[];
    __half* As0 = smh;                      // [2][BM*APH]  ([m][k])
    __half* Bs0 = smh + 2 * BM * APH;       // [2][BKH*BPH] ([k][n])

    const int tid  = threadIdx.x;
    const int lane = tid & 31;
    const int wid  = tid >> 5;
    const int warp_m = wid >> 1;            // 0..3
    const int warp_n = wid & 1;             // 0..1
    const int row0 = blockIdx.y * BM;
    const int col0 = blockIdx.x * BN;

    // A loader: 8 lanes/row, rows tid>>3 + 32p (p=0..7), cols (tid&7)*4
    const int arow = tid >> 3;              // 0..31
    const int acol = (tid & 7) * 4;         // 0..28 (floats/halves k-index)
    // B loader: 32 lanes/row, rows tid>>5 + 8p (p=0..3), cols (tid&31)*4
    const int brow = tid >> 5;              // 0..7
    const int bcol = (tid & 31) * 4;        // 0..124

    float acc[4][8][4];
#pragma unroll
    for (int mi = 0; mi < 4; ++mi)
#pragma unroll
        for (int ni = 0; ni < 8; ++ni)
#pragma unroll
            for (int e = 0; e < 4; ++e) acc[mi][ni][e] = 0.0f;

    const int nk = K / BKH;

    float4 ra[8], rb[4];
    // ---- prologue: load + stage chunk 0 ----
#pragma unroll
    for (int p = 0; p < 8; ++p)
        ra[p] = *(const float4*)(A + (size_t)(row0 + arow + 32 * p) * K + acol);
#pragma unroll
    for (int p = 0; p < 4; ++p)
        rb[p] = *(const float4*)(B + (size_t)(brow + 8 * p) * N + col0 + bcol);
#pragma unroll
    for (int p = 0; p < 8; ++p)
        *(uint2*)&As0[(arow + 32 * p) * APH + acol] = h4(ra[p]);
#pragma unroll
    for (int p = 0; p < 4; ++p)
        *(uint2*)&Bs0[(brow + 8 * p) * BPH + bcol] = h4(rb[p]);
    __syncthreads();

    const int lrow = lane & 15;
    const int lk8  = (lane & 16) ? 8 : 0;   // A: hi lanes read k+8
    const int ln8  = (lane & 16) >> 1;      // B: hi lanes read n+8

    for (int it = 0; it < nk; ++it) {
        const int cur = it & 1;

        // prefetch next chunk (gmem -> regs)
        if (it + 1 < nk) {
            const int k0 = (it + 1) * BKH;
#pragma unroll
            for (int p = 0; p < 8; ++p)
                ra[p] = *(const float4*)(A + (size_t)(row0 + arow + 32 * p) * K + k0 + acol);
#pragma unroll
            for (int p = 0; p < 4; ++p)
                rb[p] = *(const float4*)(B + (size_t)(k0 + brow + 8 * p) * N + col0 + bcol);
        }

        // ---- compute chunk it: 2 k16 steps ----
        const __half* Ac = As0 + cur * BM * APH;
        const __half* Bc = Bs0 + cur * BKH * BPH;
        const unsigned smA = (unsigned)__cvta_generic_to_shared(Ac);
        const unsigned smB = (unsigned)__cvta_generic_to_shared(Bc);
#pragma unroll
        for (int ks = 0; ks < 2; ++ks) {
            unsigned a[4][4];
#pragma unroll
            for (int mi = 0; mi < 4; ++mi) {
                unsigned ad = smA +
                    (((warp_m * 64 + mi * 16 + lrow) * APH + ks * 16 + lk8) << 1);
                asm volatile(
                    "ldmatrix.sync.aligned.m8n8.x4.shared.b16 {%0,%1,%2,%3}, [%4];"
                    : "=r"(a[mi][0]), "=r"(a[mi][1]), "=r"(a[mi][2]), "=r"(a[mi][3])
                    : "r"(ad));
            }
            // B: 4 x ldmatrix.x4.trans, group ng covers n16 at warp_n*64+ng*16
            unsigned bf[4][4];
#pragma unroll
            for (int ng = 0; ng < 4; ++ng) {
                unsigned bd = smB +
                    (((ks * 16 + lrow) * BPH + warp_n * 64 + ng * 16 + ln8) << 1);
                asm volatile(
                    "ldmatrix.sync.aligned.m8n8.x4.trans.shared.b16 {%0,%1,%2,%3}, [%4];"
                    : "=r"(bf[ng][0]), "=r"(bf[ng][1]), "=r"(bf[ng][2]), "=r"(bf[ng][3])
                    : "r"(bd));
            }
#pragma unroll
            for (int mi = 0; mi < 4; ++mi)
#pragma unroll
                for (int ni = 0; ni < 8; ++ni) {
                    const unsigned b0 = bf[ni >> 1][(ni & 1) * 2];
                    const unsigned b1 = bf[ni >> 1][(ni & 1) * 2 + 1];
                    asm volatile(
                        "mma.sync.aligned.m16n8k16.row.col.f32.f16.f16.f32 "
                        "{%0,%1,%2,%3}, {%4,%5,%6,%7}, {%8,%9}, {%0,%1,%2,%3};"
                        : "+f"(acc[mi][ni][0]), "+f"(acc[mi][ni][1]),
                          "+f"(acc[mi][ni][2]), "+f"(acc[mi][ni][3])
                        : "r"(a[mi][0]), "r"(a[mi][1]), "r"(a[mi][2]), "r"(a[mi][3]),
                          "r"(b0), "r"(b1));
                }
        }

        // stage next chunk (regs -> smem[cur^1])
        if (it + 1 < nk) {
            __half* An = As0 + (cur ^ 1) * BM * APH;
            __half* Bn = Bs0 + (cur ^ 1) * BKH * BPH;
#pragma unroll
            for (int p = 0; p < 8; ++p)
                *(uint2*)&An[(arow + 32 * p) * APH + acol] = h4(ra[p]);
#pragma unroll
            for (int p = 0; p < 4; ++p)
                *(uint2*)&Bn[(brow + 8 * p) * BPH + bcol] = h4(rb[p]);
        }
        __syncthreads();
    }

    // ---- epilogue ----
    const int g  = lane >> 2;
    const int tg = lane & 3;
#pragma unroll
    for (int mi = 0; mi < 4; ++mi) {
#pragma unroll
        for (int ni = 0; ni < 8; ++ni) {
            const int row = row0 + warp_m * 64 + mi * 16 + g;
            const int col = col0 + warp_n * 64 + ni * 8 + 2 * tg;
            *(float2*)&C[(size_t)row * N + col] =
                make_float2(acc[mi][ni][0], acc[mi][ni][1]);
            *(float2*)&C[(size_t)(row + 8) * N + col] =
                make_float2(acc[mi][ni][2], acc[mi][ni][3]);
        }
    }
}

// ===========================================================================
// Tensor-core sparse flash attention (unchanged from R10/R12 — validated).
// ===========================================================================
#define P68 68
#define ATTN_SMEM (4 * 64 * P68 * (int)sizeof(float))   // 69632 B
#define SC2 0.18033688f   // (1/sqrt(64)) * log2(e)

__global__ __launch_bounds__(128) void sparse_attn(
    const float* __restrict__ qkv, float* __restrict__ y)
{
    extern __shared__ float smf[];
    float* Qt = smf;                 // [64 q][P68]
    float* Ks = Qt + 64 * P68;       // [64 key][P68]
    float* Vt = Ks + 64 * P68;       // [64 d][P68] transposed
    float* Ps = Vt + 64 * P68;       // [64 q][P68]

    const int t    = blockIdx.x;
    const int h    = blockIdx.y;
    const int b    = blockIdx.z;
    const int tid  = threadIdx.x;
    const int lane = tid & 31;
    const int w    = tid >> 5;
    const int r0   = t * 64;

    const size_t base = (size_t)b * SEQ * QKV_LD;

    for (int e = tid; e < 1024; e += 128) {
        const int tok = e >> 4;
        const int d4  = (e & 15) * 4;
        float4 v = cvt4(*(const float4*)(qkv + base + (size_t)(r0 + tok) * QKV_LD + h * HDIM + d4));
        *(float4*)&Qt[tok * P68 + d4] = v;
    }

    const int g  = lane >> 2;
    const int tg = lane & 3;
    const int lrow = lane & 15;
    const int lk4  = (lane & 16) ? 4 : 0;

    float m0 = -3.0e38f, m1 = -3.0e38f, l0 = 0.0f, l1 = 0.0f;
    float o[8][4];
#pragma unroll
    for (int ni = 0; ni < 8; ++ni)
#pragma unroll
        for (int e = 0; e < 4; ++e) o[ni][e] = 0.0f;

    const int kb_start = (t >= 2) ? (t - 2) : 0;
    const int n_win    = t - kb_start + 1;
    const int nglob    = (t >= 3) ? (t - 2) : 0;
    const int n_tiles  = n_win + (nglob > 0 ? 1 : 0);

    const unsigned smQ = (unsigned)__cvta_generic_to_shared(Qt);
    const unsigned smP = (unsigned)__cvta_generic_to_shared(Ps);

    for (int it = 0; it < n_tiles; ++it) {
        const bool is_glob = (it == n_win);
        const int  kcol0   = (kb_start + it) * 64;

        __syncthreads();

        for (int e = tid; e < 1024; e += 128) {
            const int tok = e >> 4;
            const int d4  = (e & 15) * 4;
            int key;
            bool valid;
            if (is_glob) { key = tok * STRIDE; valid = (tok < nglob); }
            else         { key = kcol0 + tok;  valid = true; }
            float4 kv, vv;
            if (valid) {
                const float* kp = qkv + base + (size_t)key * QKV_LD + DMODEL + h * HDIM + d4;
                kv = cvt4(*(const float4*)kp);
                vv = cvt4(*(const float4*)(kp + DMODEL));
            } else {
                kv = make_float4(0.f, 0.f, 0.f, 0.f);
                vv = kv;
            }
            *(float4*)&Ks[tok * P68 + d4] = kv;
            Vt[(d4 + 0) * P68 + tok] = vv.x;
            Vt[(d4 + 1) * P68 + tok] = vv.y;
            Vt[(d4 + 2) * P68 + tok] = vv.z;
            Vt[(d4 + 3) * P68 + tok] = vv.w;
        }
        __syncthreads();

        float s[8][4];
#pragma unroll
        for (int ni = 0; ni < 8; ++ni)
#pragma unroll
            for (int e = 0; e < 4; ++e) s[ni][e] = 0.0f;

#pragma unroll
        for (int ks = 0; ks < 8; ++ks) {
            unsigned a[4];
            unsigned ad = smQ + (((w * 16 + lrow) * P68 + ks * 8 + lk4) << 2);
            asm volatile(
                "ldmatrix.sync.aligned.m8n8.x4.shared.b16 {%0,%1,%2,%3}, [%4];"
                : "=r"(a[0]), "=r"(a[1]), "=r"(a[2]), "=r"(a[3]) : "r"(ad));
            const int kk = ks * 8 + tg;
#pragma unroll
            for (int ni = 0; ni < 8; ++ni) {
                unsigned b0 = __float_as_uint(Ks[(ni * 8 + g) * P68 + kk]);
                unsigned b1 = __float_as_uint(Ks[(ni * 8 + g) * P68 + kk + 4]);
                asm volatile(
                    "mma.sync.aligned.m16n8k8.row.col.f32.tf32.tf32.f32 "
                    "{%0,%1,%2,%3}, {%4,%5,%6,%7}, {%8,%9}, {%0,%1,%2,%3};"
                    : "+f"(s[ni][0]), "+f"(s[ni][1]), "+f"(s[ni][2]), "+f"(s[ni][3])
                    : "r"(a[0]), "r"(a[1]), "r"(a[2]), "r"(a[3]), "r"(b0), "r"(b1));
            }
        }

        const int row_lo = r0 + w * 16 + g;
        const int row_hi = row_lo + 8;
#pragma unroll
        for (int ni = 0; ni < 8; ++ni) {
            const int col0 = ni * 8 + 2 * tg;
#pragma unroll
            for (int e = 0; e < 4; ++e) {
                const int col = col0 + (e & 1);
                const int row = (e < 2) ? row_lo : row_hi;
                bool ok;
                if (is_glob) {
                    ok = col < nglob;
                } else {
                    const int c = kcol0 + col;
                    ok = (c <= row) && ((row - c) <= (WINDOW - 1) || (c & (STRIDE - 1)) == 0);
                }
                s[ni][e] = ok ? s[ni][e] * SC2 : -3.0e38f;
            }
        }

        float mx0 = -3.0e38f, mx1 = -3.0e38f;
#pragma unroll
        for (int ni = 0; ni < 8; ++ni) {
            mx0 = fmaxf(mx0, fmaxf(s[ni][0], s[ni][1]));
            mx1 = fmaxf(mx1, fmaxf(s[ni][2], s[ni][3]));
        }
        mx0 = fmaxf(mx0, __shfl_xor_sync(0xffffffffu, mx0, 1));
        mx0 = fmaxf(mx0, __shfl_xor_sync(0xffffffffu, mx0, 2));
        mx1 = fmaxf(mx1, __shfl_xor_sync(0xffffffffu, mx1, 1));
        mx1 = fmaxf(mx1, __shfl_xor_sync(0xffffffffu, mx1, 2));

        const float mn0 = fmaxf(m0, mx0);
        const float mn1 = fmaxf(m1, mx1);
        const float al0 = fexp2(m0 - mn0);
        const float al1 = fexp2(m1 - mn1);

        float rs0 = 0.0f, rs1 = 0.0f;
#pragma unroll
        for (int ni = 0; ni < 8; ++ni) {
            const int col0 = ni * 8 + 2 * tg;
            float p0 = fexp2(s[ni][0] - mn0);
            float p1 = fexp2(s[ni][1] - mn0);
            float p2 = fexp2(s[ni][2] - mn1);
            float p3 = fexp2(s[ni][3] - mn1);
            rs0 += p0 + p1;
            rs1 += p2 + p3;
            float2 lo, hi;
            lo.x = __uint_as_float(f2tf(p0));
            lo.y = __uint_as_float(f2tf(p1));
            hi.x = __uint_as_float(f2tf(p2));
            hi.y = __uint_as_float(f2tf(p3));
            *(float2*)&Ps[(w * 16 + g) * P68 + col0]     = lo;
            *(float2*)&Ps[(w * 16 + g + 8) * P68 + col0] = hi;
        }
        rs0 += __shfl_xor_sync(0xffffffffu, rs0, 1);
        rs0 += __shfl_xor_sync(0xffffffffu, rs0, 2);
        rs1 += __shfl_xor_sync(0xffffffffu, rs1, 1);
        rs1 += __shfl_xor_sync(0xffffffffu, rs1, 2);

        l0 = l0 * al0 + rs0;
        l1 = l1 * al1 + rs1;
        m0 = mn0;
        m1 = mn1;
#pragma unroll
        for (int ni = 0; ni < 8; ++ni) {
            o[ni][0] *= al0;
            o[ni][1] *= al0;
            o[ni][2] *= al1;
            o[ni][3] *= al1;
        }
        __syncwarp();

#pragma unroll
        for (int ks = 0; ks < 8; ++ks) {
            unsigned a[4];
            unsigned ad = smP + (((w * 16 + lrow) * P68 + ks * 8 + lk4) << 2);
            asm volatile(
                "ldmatrix.sync.aligned.m8n8.x4.shared.b16 {%0,%1,%2,%3}, [%4];"
                : "=r"(a[0]), "=r"(a[1]), "=r"(a[2]), "=r"(a[3]) : "r"(ad));
            const int kk = ks * 8 + tg;
#pragma unroll
            for (int ni = 0; ni < 8; ++ni) {
                unsigned b0 = __float_as_uint(Vt[(ni * 8 + g) * P68 + kk]);
                unsigned b1 = __float_as_uint(Vt[(ni * 8 + g) * P68 + kk + 4]);
                asm volatile(
                    "mma.sync.aligned.m16n8k8.row.col.f32.tf32.tf32.f32 "
                    "{%0,%1,%2,%3}, {%4,%5,%6,%7}, {%8,%9}, {%0,%1,%2,%3};"
                    : "+f"(o[ni][0]), "+f"(o[ni][1]), "+f"(o[ni][2]), "+f"(o[ni][3])
                    : "r"(a[0]), "r"(a[1]), "r"(a[2]), "r"(a[3]), "r"(b0), "r"(b1));
            }
        }
        __syncwarp();
    }

    const float inv0 = 1.0f / l0;
    const float inv1 = 1.0f / l1;
    const size_t row_lo = (size_t)b * SEQ + r0 + w * 16 + g;
#pragma unroll
    for (int ni = 0; ni < 8; ++ni) {
        const int col = h * HDIM + ni * 8 + 2 * tg;
        *(float2*)&y[row_lo * DMODEL + col] =
            make_float2(o[ni][0] * inv0, o[ni][1] * inv0);
        *(float2*)&y[(row_lo + 8) * DMODEL + col] =
            make_float2(o[ni][2] * inv1, o[ni][3] * inv1);
    }
}

// ---------------------------------------------------------------------------
extern "C" void kernel_launch(void* const* d_in, const int* in_sizes, int n_in,
                              void* d_out, int out_size)
{
    const float* x     = (const float*)d_in[0];
    const float* Wqkv  = (const float*)d_in[1];
    const float* Wproj = (const float*)d_in[2];
    float* out = (float*)d_out;

    float *qkv = nullptr, *y = nullptr;
    cudaGetSymbolAddress((void**)&qkv, g_qkv);
    cudaGetSymbolAddress((void**)&y, g_y);

    cudaFuncSetAttribute(hgemm, cudaFuncAttributeMaxDynamicSharedMemorySize, GEMM_SMEM);
    cudaFuncSetAttribute(sparse_attn, cudaFuncAttributeMaxDynamicSharedMemorySize, ATTN_SMEM);

    // 1) QKV projection: [4096,1024] @ [1024,3072]  (fp16 mma, fp32 accum)
    hgemm<<<dim3(QKV_LD / BN, NTOK / BM), 256, GEMM_SMEM>>>(x, Wqkv, qkv, NTOK, QKV_LD, DMODEL);

    // 2) Sparse attention (tf32 tensor cores)
    sparse_attn<<<dim3(SEQ / 64, NHEADS, BATCH), 128, ATTN_SMEM>>>(qkv, y);

    // 3) Output projection: [4096,1024] @ [1024,1024]  (fp16 mma, fp32 accum)
    hgemm<<<dim3(DMODEL / BN, NTOK / BM), 256, GEMM_SMEM>>>(y, Wproj, out, NTOK, DMODEL, DMODEL);
}

// round 14
// speedup vs baseline: 2.5192x; 1.1626x over previous
#include <cuda_runtime.h>
#include <cuda_fp16.h>
#include <cstdint>
#include <cfloat>

// Problem constants
#define BATCH   2
#define SEQ     2048
#define DMODEL  1024
#define NHEADS  16
#define HDIM    64
#define QKV_LD  3072
#define NTOK    (BATCH * SEQ)      // 4096
#define WINDOW  128
#define STRIDE  64

// Scratch (device globals: no allocation allowed)
__device__ float g_qkv[(size_t)NTOK * QKV_LD];   // 4096 x 3072
__device__ float g_y[(size_t)NTOK * DMODEL];     // 4096 x 1024

// pack two floats into half2 bits (x -> low, y -> high)
__device__ __forceinline__ unsigned f2h2(float x, float y) {
    __half2 h = __float22half2_rn(make_float2(x, y));
    return *reinterpret_cast<unsigned*>(&h);
}
__device__ __forceinline__ uint2 h4(float4 v) {
    return make_uint2(f2h2(v.x, v.y), f2h2(v.z, v.w));
}
// Fast exp2 on the FMA pipe (x <= 0; clamped at -126). Rel err < 1e-4.
__device__ __forceinline__ float fexp2(float x) {
    x = fmaxf(x, -126.0f);
    float n = floorf(x);
    float f = x - n;
    float p = 0.00133336f;
    p = fmaf(p, f, 0.00961813f);
    p = fmaf(p, f, 0.05550411f);
    p = fmaf(p, f, 0.24022651f);
    p = fmaf(p, f, 0.69314718f);
    p = fmaf(p, f, 1.0f);
    return __int_as_float(((int)n + 127) << 23) * p;
}

// ===========================================================================
// FP16 mma.sync GEMM (m16n8k16, fp32 accum) — R13 config, UNCHANGED.
// CTA 256x128, BK=32, 256 threads = 8 warps (4M x 2N), warp tile 64x64.
// Coalesced loaders (nL=4). A staged [m][k] pitch 40; B [k][n] pitch 136.
// ===========================================================================
#define BM 256
#define BN 128
#define BKH 32
#define APH 40
#define BPH 136
#define GEMM_SMEM ((2 * (BM * APH + BKH * BPH)) * (int)sizeof(__half))  // 58368

__global__ __launch_bounds__(256, 1) void hgemm(
    const float* __restrict__ A, const float* __restrict__ B,
    float* __restrict__ C, int M, int N, int K)
{
    extern __shared__ __half smh[];
    __half* As0 = smh;                      // [2][BM*APH]  ([m][k])
    __half* Bs0 = smh + 2 * BM * APH;       // [2][BKH*BPH] ([k][n])

    const int tid  = threadIdx.x;
    const int lane = tid & 31;
    const int wid  = tid >> 5;
    const int warp_m = wid >> 1;
    const int warp_n = wid & 1;
    const int row0 = blockIdx.y * BM;
    const int col0 = blockIdx.x * BN;

    const int arow = tid >> 3;              // 0..31
    const int acol = (tid & 7) * 4;         // 0..28
    const int brow = tid >> 5;              // 0..7
    const int bcol = (tid & 31) * 4;        // 0..124

    float acc[4][8][4];
#pragma unroll
    for (int mi = 0; mi < 4; ++mi)
#pragma unroll
        for (int ni = 0; ni < 8; ++ni)
#pragma unroll
            for (int e = 0; e < 4; ++e) acc[mi][ni][e] = 0.0f;

    const int nk = K / BKH;

    float4 ra[8], rb[4];
#pragma unroll
    for (int p = 0; p < 8; ++p)
        ra[p] = *(const float4*)(A + (size_t)(row0 + arow + 32 * p) * K + acol);
#pragma unroll
    for (int p = 0; p < 4; ++p)
        rb[p] = *(const float4*)(B + (size_t)(brow + 8 * p) * N + col0 + bcol);
#pragma unroll
    for (int p = 0; p < 8; ++p)
        *(uint2*)&As0[(arow + 32 * p) * APH + acol] = h4(ra[p]);
#pragma unroll
    for (int p = 0; p < 4; ++p)
        *(uint2*)&Bs0[(brow + 8 * p) * BPH + bcol] = h4(rb[p]);
    __syncthreads();

    const int lrow = lane & 15;
    const int lk8  = (lane & 16) ? 8 : 0;
    const int ln8  = (lane & 16) >> 1;

    for (int it = 0; it < nk; ++it) {
        const int cur = it & 1;

        if (it + 1 < nk) {
            const int k0 = (it + 1) * BKH;
#pragma unroll
            for (int p = 0; p < 8; ++p)
                ra[p] = *(const float4*)(A + (size_t)(row0 + arow + 32 * p) * K + k0 + acol);
#pragma unroll
            for (int p = 0; p < 4; ++p)
                rb[p] = *(const float4*)(B + (size_t)(k0 + brow + 8 * p) * N + col0 + bcol);
        }

        const __half* Ac = As0 + cur * BM * APH;
        const __half* Bc = Bs0 + cur * BKH * BPH;
        const unsigned smA = (unsigned)__cvta_generic_to_shared(Ac);
        const unsigned smB = (unsigned)__cvta_generic_to_shared(Bc);
#pragma unroll
        for (int ks = 0; ks < 2; ++ks) {
            unsigned a[4][4];
#pragma unroll
            for (int mi = 0; mi < 4; ++mi) {
                unsigned ad = smA +
                    (((warp_m * 64 + mi * 16 + lrow) * APH + ks * 16 + lk8) << 1);
                asm volatile(
                    "ldmatrix.sync.aligned.m8n8.x4.shared.b16 {%0,%1,%2,%3}, [%4];"
                    : "=r"(a[mi][0]), "=r"(a[mi][1]), "=r"(a[mi][2]), "=r"(a[mi][3])
                    : "r"(ad));
            }
            unsigned bf[4][4];
#pragma unroll
            for (int ng = 0; ng < 4; ++ng) {
                unsigned bd = smB +
                    (((ks * 16 + lrow) * BPH + warp_n * 64 + ng * 16 + ln8) << 1);
                asm volatile(
                    "ldmatrix.sync.aligned.m8n8.x4.trans.shared.b16 {%0,%1,%2,%3}, [%4];"
                    : "=r"(bf[ng][0]), "=r"(bf[ng][1]), "=r"(bf[ng][2]), "=r"(bf[ng][3])
                    : "r"(bd));
            }
#pragma unroll
            for (int mi = 0; mi < 4; ++mi)
#pragma unroll
                for (int ni = 0; ni < 8; ++ni) {
                    const unsigned b0 = bf[ni >> 1][(ni & 1) * 2];
                    const unsigned b1 = bf[ni >> 1][(ni & 1) * 2 + 1];
                    asm volatile(
                        "mma.sync.aligned.m16n8k16.row.col.f32.f16.f16.f32 "
                        "{%0,%1,%2,%3}, {%4,%5,%6,%7}, {%8,%9}, {%0,%1,%2,%3};"
                        : "+f"(acc[mi][ni][0]), "+f"(acc[mi][ni][1]),
                          "+f"(acc[mi][ni][2]), "+f"(acc[mi][ni][3])
                        : "r"(a[mi][0]), "r"(a[mi][1]), "r"(a[mi][2]), "r"(a[mi][3]),
                          "r"(b0), "r"(b1));
                }
        }

        if (it + 1 < nk) {
            __half* An = As0 + (cur ^ 1) * BM * APH;
            __half* Bn = Bs0 + (cur ^ 1) * BKH * BPH;
#pragma unroll
            for (int p = 0; p < 8; ++p)
                *(uint2*)&An[(arow + 32 * p) * APH + acol] = h4(ra[p]);
#pragma unroll
            for (int p = 0; p < 4; ++p)
                *(uint2*)&Bn[(brow + 8 * p) * BPH + bcol] = h4(rb[p]);
        }
        __syncthreads();
    }

    const int g  = lane >> 2;
    const int tg = lane & 3;
#pragma unroll
    for (int mi = 0; mi < 4; ++mi) {
#pragma unroll
        for (int ni = 0; ni < 8; ++ni) {
            const int row = row0 + warp_m * 64 + mi * 16 + g;
            const int col = col0 + warp_n * 64 + ni * 8 + 2 * tg;
            *(float2*)&C[(size_t)row * N + col] =
                make_float2(acc[mi][ni][0], acc[mi][ni][1]);
            *(float2*)&C[(size_t)(row + 8) * N + col] =
                make_float2(acc[mi][ni][2], acc[mi][ni][3]);
        }
    }
}

// ===========================================================================
// FP16 tensor-core sparse flash attention (R14).
// Grid (S/64, H, B), 128 threads = 4 warps; warp w owns query rows 16w..16w+15.
// S = Q K^T and O += P V via m16n8k16 fp16 mma (fragment patterns identical
// to validated hgemm). Smem (halves, pitch 72): Qh[q][d], Kt[d][key],
// Vh[key][d], Ph[q][key]. 36.9KB -> 6 CTAs/SM.
// ===========================================================================
#define P72 72
#define ATTN_SMEM (4 * 64 * P72 * (int)sizeof(__half))   // 36864 B
#define SC2 0.18033688f   // (1/sqrt(64)) * log2(e)

__global__ __launch_bounds__(128) void sparse_attn(
    const float* __restrict__ qkv, float* __restrict__ y)
{
    extern __shared__ __half smha[];
    __half* Qh = smha;               // [64 q][P72]
    __half* Kt = Qh + 64 * P72;      // [64 d][P72]   (K transposed: row=d, col=key)
    __half* Vh = Kt + 64 * P72;      // [64 key][P72] (natural: row=key, col=d)
    __half* Ph = Vh + 64 * P72;      // [64 q][P72]

    const int t    = blockIdx.x;
    const int h    = blockIdx.y;
    const int b    = blockIdx.z;
    const int tid  = threadIdx.x;
    const int lane = tid & 31;
    const int w    = tid >> 5;
    const int r0   = t * 64;

    const size_t base = (size_t)b * SEQ * QKV_LD;

    // ---- stage Q (fp16) ----
    for (int e = tid; e < 1024; e += 128) {
        const int tok = e >> 4;
        const int d4  = (e & 15) * 4;
        float4 v = *(const float4*)(qkv + base + (size_t)(r0 + tok) * QKV_LD + h * HDIM + d4);
        *(uint2*)&Qh[tok * P72 + d4] = h4(v);
    }

    const int g  = lane >> 2;
    const int tg = lane & 3;
    const int lrow = lane & 15;
    const int lk8  = (lane & 16) ? 8 : 0;
    const int ln8  = (lane & 16) >> 1;

    float m0 = -3.0e38f, m1 = -3.0e38f, l0 = 0.0f, l1 = 0.0f;
    float o[8][4];
#pragma unroll
    for (int ni = 0; ni < 8; ++ni)
#pragma unroll
        for (int e = 0; e < 4; ++e) o[ni][e] = 0.0f;

    const int kb_start = (t >= 2) ? (t - 2) : 0;
    const int n_win    = t - kb_start + 1;
    const int nglob    = (t >= 3) ? (t - 2) : 0;
    const int n_tiles  = n_win + (nglob > 0 ? 1 : 0);

    const unsigned smQ = (unsigned)__cvta_generic_to_shared(Qh);
    const unsigned smK = (unsigned)__cvta_generic_to_shared(Kt);
    const unsigned smV = (unsigned)__cvta_generic_to_shared(Vh);
    const unsigned smP = (unsigned)__cvta_generic_to_shared(Ph);

    for (int it = 0; it < n_tiles; ++it) {
        const bool is_glob = (it == n_win);
        const int  kcol0   = (kb_start + it) * 64;

        __syncthreads();   // prior tile's mma reads of Kt/Vh done (covers Q on it=0)

        // ---- stage K transposed [d][key] and V natural [key][d] ----
        for (int e = tid; e < 1024; e += 128) {
            const int tok = e >> 4;
            const int d4  = (e & 15) * 4;
            int key;
            bool valid;
            if (is_glob) { key = tok * STRIDE; valid = (tok < nglob); }
            else         { key = kcol0 + tok;  valid = true; }
            float4 kv, vv;
            if (valid) {
                const float* kp = qkv + base + (size_t)key * QKV_LD + DMODEL + h * HDIM + d4;
                kv = *(const float4*)kp;
                vv = *(const float4*)(kp + DMODEL);
            } else {
                kv = make_float4(0.f, 0.f, 0.f, 0.f);
                vv = kv;
            }
            Kt[(d4 + 0) * P72 + tok] = __float2half_rn(kv.x);
            Kt[(d4 + 1) * P72 + tok] = __float2half_rn(kv.y);
            Kt[(d4 + 2) * P72 + tok] = __float2half_rn(kv.z);
            Kt[(d4 + 3) * P72 + tok] = __float2half_rn(kv.w);
            *(uint2*)&Vh[tok * P72 + d4] = h4(vv);
        }
        __syncthreads();

        // ---- S = Q K^T (fp16 mma, k=d=64 -> 4 k16 steps) ----
        float s[8][4];
#pragma unroll
        for (int ni = 0; ni < 8; ++ni)
#pragma unroll
            for (int e = 0; e < 4; ++e) s[ni][e] = 0.0f;

#pragma unroll
        for (int ks = 0; ks < 4; ++ks) {
            unsigned a[4];
            unsigned ad = smQ + (((w * 16 + lrow) * P72 + ks * 16 + lk8) << 1);
            asm volatile(
                "ldmatrix.sync.aligned.m8n8.x4.shared.b16 {%0,%1,%2,%3}, [%4];"
                : "=r"(a[0]), "=r"(a[1]), "=r"(a[2]), "=r"(a[3]) : "r"(ad));
            unsigned bf[4][4];
#pragma unroll
            for (int ng = 0; ng < 4; ++ng) {
                unsigned bd = smK + (((ks * 16 + lrow) * P72 + ng * 16 + ln8) << 1);
                asm volatile(
                    "ldmatrix.sync.aligned.m8n8.x4.trans.shared.b16 {%0,%1,%2,%3}, [%4];"
                    : "=r"(bf[ng][0]), "=r"(bf[ng][1]), "=r"(bf[ng][2]), "=r"(bf[ng][3])
                    : "r"(bd));
            }
#pragma unroll
            for (int ni = 0; ni < 8; ++ni) {
                const unsigned b0 = bf[ni >> 1][(ni & 1) * 2];
                const unsigned b1 = bf[ni >> 1][(ni & 1) * 2 + 1];
                asm volatile(
                    "mma.sync.aligned.m16n8k16.row.col.f32.f16.f16.f32 "
                    "{%0,%1,%2,%3}, {%4,%5,%6,%7}, {%8,%9}, {%0,%1,%2,%3};"
                    : "+f"(s[ni][0]), "+f"(s[ni][1]), "+f"(s[ni][2]), "+f"(s[ni][3])
                    : "r"(a[0]), "r"(a[1]), "r"(a[2]), "r"(a[3]), "r"(b0), "r"(b1));
            }
        }

        // ---- mask + scale (base-2 domain) ----
        const int row_lo = r0 + w * 16 + g;
        const int row_hi = row_lo + 8;
#pragma unroll
        for (int ni = 0; ni < 8; ++ni) {
            const int col0 = ni * 8 + 2 * tg;
#pragma unroll
            for (int e = 0; e < 4; ++e) {
                const int col = col0 + (e & 1);
                const int row = (e < 2) ? row_lo : row_hi;
                bool ok;
                if (is_glob) {
                    ok = col < nglob;
                } else {
                    const int c = kcol0 + col;
                    ok = (c <= row) && ((row - c) <= (WINDOW - 1) || (c & (STRIDE - 1)) == 0);
                }
                s[ni][e] = ok ? s[ni][e] * SC2 : -3.0e38f;
            }
        }

        // ---- online softmax on fragments ----
        float mx0 = -3.0e38f, mx1 = -3.0e38f;
#pragma unroll
        for (int ni = 0; ni < 8; ++ni) {
            mx0 = fmaxf(mx0, fmaxf(s[ni][0], s[ni][1]));
            mx1 = fmaxf(mx1, fmaxf(s[ni][2], s[ni][3]));
        }
        mx0 = fmaxf(mx0, __shfl_xor_sync(0xffffffffu, mx0, 1));
        mx0 = fmaxf(mx0, __shfl_xor_sync(0xffffffffu, mx0, 2));
        mx1 = fmaxf(mx1, __shfl_xor_sync(0xffffffffu, mx1, 1));
        mx1 = fmaxf(mx1, __shfl_xor_sync(0xffffffffu, mx1, 2));

        const float mn0 = fmaxf(m0, mx0);
        const float mn1 = fmaxf(m1, mx1);
        const float al0 = fexp2(m0 - mn0);
        const float al1 = fexp2(m1 - mn1);

        float rs0 = 0.0f, rs1 = 0.0f;
#pragma unroll
        for (int ni = 0; ni < 8; ++ni) {
            const int col0 = ni * 8 + 2 * tg;
            float p0 = fexp2(s[ni][0] - mn0);
            float p1 = fexp2(s[ni][1] - mn0);
            float p2 = fexp2(s[ni][2] - mn1);
            float p3 = fexp2(s[ni][3] - mn1);
            rs0 += p0 + p1;
            rs1 += p2 + p3;
            *(unsigned*)&Ph[(w * 16 + g) * P72 + col0]     = f2h2(p0, p1);
            *(unsigned*)&Ph[(w * 16 + g + 8) * P72 + col0] = f2h2(p2, p3);
        }
        rs0 += __shfl_xor_sync(0xffffffffu, rs0, 1);
        rs0 += __shfl_xor_sync(0xffffffffu, rs0, 2);
        rs1 += __shfl_xor_sync(0xffffffffu, rs1, 1);
        rs1 += __shfl_xor_sync(0xffffffffu, rs1, 2);

        l0 = l0 * al0 + rs0;
        l1 = l1 * al1 + rs1;
        m0 = mn0;
        m1 = mn1;
#pragma unroll
        for (int ni = 0; ni < 8; ++ni) {
            o[ni][0] *= al0;
            o[ni][1] *= al0;
            o[ni][2] *= al1;
            o[ni][3] *= al1;
        }
        __syncwarp();

        // ---- O += P V (fp16 mma, k=key=64 -> 4 k16 steps) ----
#pragma unroll
        for (int ks = 0; ks < 4; ++ks) {
            unsigned a[4];
            unsigned ad = smP + (((w * 16 + lrow) * P72 + ks * 16 + lk8) << 1);
            asm volatile(
                "ldmatrix.sync.aligned.m8n8.x4.shared.b16 {%0,%1,%2,%3}, [%4];"
                : "=r"(a[0]), "=r"(a[1]), "=r"(a[2]), "=r"(a[3]) : "r"(ad));
            unsigned bf[4][4];
#pragma unroll
            for (int ng = 0; ng < 4; ++ng) {
                unsigned bd = smV + (((ks * 16 + lrow) * P72 + ng * 16 + ln8) << 1);
                asm volatile(
                    "ldmatrix.sync.aligned.m8n8.x4.trans.shared.b16 {%0,%1,%2,%3}, [%4];"
                    : "=r"(bf[ng][0]), "=r"(bf[ng][1]), "=r"(bf[ng][2]), "=r"(bf[ng][3])
                    : "r"(bd));
            }
#pragma unroll
            for (int ni = 0; ni < 8; ++ni) {
                const unsigned b0 = bf[ni >> 1][(ni & 1) * 2];
                const unsigned b1 = bf[ni >> 1][(ni & 1) * 2 + 1];
                asm volatile(
                    "mma.sync.aligned.m16n8k16.row.col.f32.f16.f16.f32 "
                    "{%0,%1,%2,%3}, {%4,%5,%6,%7}, {%8,%9}, {%0,%1,%2,%3};"
                    : "+f"(o[ni][0]), "+f"(o[ni][1]), "+f"(o[ni][2]), "+f"(o[ni][3])
                    : "r"(a[0]), "r"(a[1]), "r"(a[2]), "r"(a[3]), "r"(b0), "r"(b1));
            }
        }
        __syncwarp();
    }

    // ---- epilogue: normalize + write y ----
    const float inv0 = 1.0f / l0;
    const float inv1 = 1.0f / l1;
    const size_t row_lo = (size_t)b * SEQ + r0 + w * 16 + g;
#pragma unroll
    for (int ni = 0; ni < 8; ++ni) {
        const int col = h * HDIM + ni * 8 + 2 * tg;
        *(float2*)&y[row_lo * DMODEL + col] =
            make_float2(o[ni][0] * inv0, o[ni][1] * inv0);
        *(float2*)&y[(row_lo + 8) * DMODEL + col] =
            make_float2(o[ni][2] * inv1, o[ni][3] * inv1);
    }
}

// ---------------------------------------------------------------------------
extern "C" void kernel_launch(void* const* d_in, const int* in_sizes, int n_in,
                              void* d_out, int out_size)
{
    const float* x     = (const float*)d_in[0];
    const float* Wqkv  = (const float*)d_in[1];
    const float* Wproj = (const float*)d_in[2];
    float* out = (float*)d_out;

    float *qkv = nullptr, *y = nullptr;
    cudaGetSymbolAddress((void**)&qkv, g_qkv);
    cudaGetSymbolAddress((void**)&y, g_y);

    cudaFuncSetAttribute(hgemm, cudaFuncAttributeMaxDynamicSharedMemorySize, GEMM_SMEM);
    cudaFuncSetAttribute(sparse_attn, cudaFuncAttributeMaxDynamicSharedMemorySize, ATTN_SMEM);

    // 1) QKV projection: [4096,1024] @ [1024,3072]  (fp16 mma, fp32 accum)
    hgemm<<<dim3(QKV_LD / BN, NTOK / BM), 256, GEMM_SMEM>>>(x, Wqkv, qkv, NTOK, QKV_LD, DMODEL);

    // 2) Sparse attention (fp16 tensor cores)
    sparse_attn<<<dim3(SEQ / 64, NHEADS, BATCH), 128, ATTN_SMEM>>>(qkv, y);

    // 3) Output projection: [4096,1024] @ [1024,1024]  (fp16 mma, fp32 accum)
    hgemm<<<dim3(DMODEL / BN, NTOK / BM), 256, GEMM_SMEM>>>(y, Wproj, out, NTOK, DMODEL, DMODEL);
}

// round 15
// speedup vs baseline: 2.7403x; 1.0878x over previous
#include <cuda_runtime.h>
#include <cuda_fp16.h>
#include <cstdint>
#include <cfloat>

// Problem constants
#define BATCH   2
#define SEQ     2048
#define DMODEL  1024
#define NHEADS  16
#define HDIM    64
#define QKV_LD  3072
#define NTOK    (BATCH * SEQ)      // 4096
#define WINDOW  128
#define STRIDE  64

// Scratch (device globals: no allocation allowed) — fp16 dataflow
__device__ __half g_xh[(size_t)NTOK * DMODEL];      // x (half)
__device__ __half g_wqkvh[(size_t)DMODEL * QKV_LD]; // Wqkv (half)
__device__ __half g_wph[(size_t)DMODEL * DMODEL];   // Wproj (half)
__device__ __half g_qkvh[(size_t)NTOK * QKV_LD];    // qkv (half)
__device__ __half g_yh[(size_t)NTOK * DMODEL];      // y (half)

// pack two floats into half2 bits
__device__ __forceinline__ unsigned f2h2(float x, float y) {
    __half2 h = __float22half2_rn(make_float2(x, y));
    return *reinterpret_cast<unsigned*>(&h);
}
__device__ __forceinline__ uint2 h4(float4 v) {
    return make_uint2(f2h2(v.x, v.y), f2h2(v.z, v.w));
}
// Fast exp2 on the FMA pipe (x <= 0; clamped at -126). Rel err < 1e-4.
__device__ __forceinline__ float fexp2(float x) {
    x = fmaxf(x, -126.0f);
    float n = floorf(x);
    float f = x - n;
    float p = 0.00133336f;
    p = fmaf(p, f, 0.00961813f);
    p = fmaf(p, f, 0.05550411f);
    p = fmaf(p, f, 0.24022651f);
    p = fmaf(p, f, 0.69314718f);
    p = fmaf(p, f, 1.0f);
    return __int_as_float(((int)n + 127) << 23) * p;
}

// ---------------------------------------------------------------------------
// Fused fp32->fp16 convert for x, Wqkv, Wproj (ONE launch, ~50MB traffic).
// ---------------------------------------------------------------------------
__global__ __launch_bounds__(256) void cvt_all(
    const float4* __restrict__ a, uint2* __restrict__ oa, int na,
    const float4* __restrict__ b, uint2* __restrict__ ob, int nb,
    const float4* __restrict__ c, uint2* __restrict__ oc, int nc)
{
    const int total = na + nb + nc;
    for (int i = blockIdx.x * blockDim.x + threadIdx.x; i < total;
         i += gridDim.x * blockDim.x) {
        if (i < na)            oa[i]           = h4(a[i]);
        else if (i < na + nb)  ob[i - na]      = h4(b[i - na]);
        else                   oc[i - na - nb] = h4(c[i - na - nb]);
    }
}

// ===========================================================================
// FP16 mma.sync GEMM v2 (cp.async): C[M,N] = A[M,K] @ B[K,N], half inputs.
// CTA 128x128, BK=32, 256 threads = 8 warps (2M x 4N), warp tile 64x32.
// 4-stage cp.async ring (75.8KB smem), __launch_bounds__(256,2) -> 2 CTAs/SM.
// A staged [m][k] pitch 40 halves; B [k][n] pitch 136 halves (validated
// ldmatrix-conflict-free pitches). OutT = __half (QKV) or float (proj).
// Requires M%128==0, N%128==0, K%32==0, K>=96.
// ===========================================================================
#define BMh 128
#define BNh 128
#define BKh 32
#define APh 40     // A pitch (halves): 80B row stride
#define BPh 136    // B pitch (halves): 272B row stride
#define HSTAGES 4
#define HSTG_A (BMh * APh)   // 5120 halves
#define HSTG_B (BKh * BPh)   // 4352 halves
#define GEMM_SMEM (HSTAGES * (HSTG_A + HSTG_B) * (int)sizeof(__half))  // 75776

__device__ __forceinline__ void cp16h(uint32_t dst, const __half* src) {
    asm volatile("cp.async.ca.shared.global [%0], [%1], 16;"
                 :: "r"(dst), "l"(src) : "memory");
}

// 256-thread stage issue: A 128x32 halves (8KB), B 32x128 halves (8KB).
__device__ __forceinline__ void issue_stage_h(
    const __half* __restrict__ A, const __half* __restrict__ B,
    __half* As, __half* Bs, int row0, int col0, int k0, int tid, int N, int K)
{
    // A: 4 lanes/row (16B chunks), rows tid>>2 + 64p
    const int arow = tid >> 2;            // 0..63
    const int ach  = (tid & 3) * 8;       // halves offset: 0,8,16,24
#pragma unroll
    for (int p = 0; p < 2; ++p) {
        const int r = arow + 64 * p;
        uint32_t d = (uint32_t)__cvta_generic_to_shared(&As[r * APh + ach]);
        cp16h(d, A + (size_t)(row0 + r) * K + k0 + ach);
    }
    // B: 16 lanes/row (16B chunks), rows tid>>4 + 16p
    const int brow = tid >> 4;            // 0..15
    const int bch  = (tid & 15) * 8;      // 0..120
#pragma unroll
    for (int p = 0; p < 2; ++p) {
        const int r = brow + 16 * p;
        uint32_t d = (uint32_t)__cvta_generic_to_shared(&Bs[r * BPh + bch]);
        cp16h(d, B + (size_t)(k0 + r) * N + col0 + bch);
    }
}

template<typename OutT>
__global__ __launch_bounds__(256, 2) void hgemm(
    const __half* __restrict__ A, const __half* __restrict__ B,
    OutT* __restrict__ C, int M, int N, int K)
{
    extern __shared__ __half smh[];
    __half* As0 = smh;                        // [HSTAGES][HSTG_A]
    __half* Bs0 = smh + HSTAGES * HSTG_A;     // [HSTAGES][HSTG_B]

    const int tid  = threadIdx.x;
    const int lane = tid & 31;
    const int wid  = tid >> 5;
    const int warp_m = wid >> 2;              // 0..1
    const int warp_n = wid & 3;               // 0..3
    const int row0 = blockIdx.y * BMh;
    const int col0 = blockIdx.x * BNh;

    float acc[4][4][4];
#pragma unroll
    for (int mi = 0; mi < 4; ++mi)
#pragma unroll
        for (int ni = 0; ni < 4; ++ni)
#pragma unroll
            for (int e = 0; e < 4; ++e) acc[mi][ni][e] = 0.0f;

    const int nk = K / BKh;

    // prologue: issue 3 stages
#pragma unroll
    for (int s = 0; s < HSTAGES - 1; ++s) {
        issue_stage_h(A, B, As0 + s * HSTG_A, Bs0 + s * HSTG_B,
                      row0, col0, s * BKh, tid, N, K);
        asm volatile("cp.async.commit_group;" ::: "memory");
    }

    const int lrow = lane & 15;
    const int lk8  = (lane & 16) ? 8 : 0;
    const int ln8  = (lane & 16) >> 1;

    for (int it = 0; it < nk; ++it) {
        const int cur = it & (HSTAGES - 1);

        asm volatile("cp.async.wait_group 2;" ::: "memory");
        __syncthreads();

        if (it + HSTAGES - 1 < nk) {
            const int nb = (it + HSTAGES - 1) & (HSTAGES - 1);
            issue_stage_h(A, B, As0 + nb * HSTG_A, Bs0 + nb * HSTG_B,
                          row0, col0, (it + HSTAGES - 1) * BKh, tid, N, K);
        }
        asm volatile("cp.async.commit_group;" ::: "memory");

        const __half* Ac = As0 + cur * HSTG_A;
        const __half* Bc = Bs0 + cur * HSTG_B;
        const unsigned smA = (unsigned)__cvta_generic_to_shared(Ac);
        const unsigned smB = (unsigned)__cvta_generic_to_shared(Bc);
#pragma unroll
        for (int ks = 0; ks < 2; ++ks) {
            unsigned a[4][4];
#pragma unroll
            for (int mi = 0; mi < 4; ++mi) {
                unsigned ad = smA +
                    (((warp_m * 64 + mi * 16 + lrow) * APh + ks * 16 + lk8) << 1);
                asm volatile(
                    "ldmatrix.sync.aligned.m8n8.x4.shared.b16 {%0,%1,%2,%3}, [%4];"
                    : "=r"(a[mi][0]), "=r"(a[mi][1]), "=r"(a[mi][2]), "=r"(a[mi][3])
                    : "r"(ad));
            }
            unsigned bf[2][4];
#pragma unroll
            for (int ng = 0; ng < 2; ++ng) {
                unsigned bd = smB +
                    (((ks * 16 + lrow) * BPh + warp_n * 32 + ng * 16 + ln8) << 1);
                asm volatile(
                    "ldmatrix.sync.aligned.m8n8.x4.trans.shared.b16 {%0,%1,%2,%3}, [%4];"
                    : "=r"(bf[ng][0]), "=r"(bf[ng][1]), "=r"(bf[ng][2]), "=r"(bf[ng][3])
                    : "r"(bd));
            }
#pragma unroll
            for (int mi = 0; mi < 4; ++mi)
#pragma unroll
                for (int ni = 0; ni < 4; ++ni) {
                    const unsigned b0 = bf[ni >> 1][(ni & 1) * 2];
                    const unsigned b1 = bf[ni >> 1][(ni & 1) * 2 + 1];
                    asm volatile(
                        "mma.sync.aligned.m16n8k16.row.col.f32.f16.f16.f32 "
                        "{%0,%1,%2,%3}, {%4,%5,%6,%7}, {%8,%9}, {%0,%1,%2,%3};"
                        : "+f"(acc[mi][ni][0]), "+f"(acc[mi][ni][1]),
                          "+f"(acc[mi][ni][2]), "+f"(acc[mi][ni][3])
                        : "r"(a[mi][0]), "r"(a[mi][1]), "r"(a[mi][2]), "r"(a[mi][3]),
                          "r"(b0), "r"(b1));
                }
        }
    }

    // ---- epilogue ----
    const int g  = lane >> 2;
    const int tg = lane & 3;
#pragma unroll
    for (int mi = 0; mi < 4; ++mi) {
#pragma unroll
        for (int ni = 0; ni < 4; ++ni) {
            const int row = row0 + warp_m * 64 + mi * 16 + g;
            const int col = col0 + warp_n * 32 + ni * 8 + 2 * tg;
            if constexpr (sizeof(OutT) == 2) {
                *(unsigned*)((__half*)C + (size_t)row * N + col) =
                    f2h2(acc[mi][ni][0], acc[mi][ni][1]);
                *(unsigned*)((__half*)C + (size_t)(row + 8) * N + col) =
                    f2h2(acc[mi][ni][2], acc[mi][ni][3]);
            } else {
                *(float2*)((float*)C + (size_t)row * N + col) =
                    make_float2(acc[mi][ni][0], acc[mi][ni][1]);
                *(float2*)((float*)C + (size_t)(row + 8) * N + col) =
                    make_float2(acc[mi][ni][2], acc[mi][ni][3]);
            }
        }
    }
}

// ===========================================================================
// FP16 tensor-core sparse flash attention (R14 validated, half qkv in/out).
// ===========================================================================
#define P72 72
#define ATTN_SMEM (4 * 64 * P72 * (int)sizeof(__half))   // 36864 B
#define SC2 0.18033688f   // (1/sqrt(64)) * log2(e)

__global__ __launch_bounds__(128) void sparse_attn(
    const __half* __restrict__ qkvh, __half* __restrict__ yh)
{
    extern __shared__ __half smha[];
    __half* Qh = smha;               // [64 q][P72]
    __half* Kt = Qh + 64 * P72;      // [64 d][P72]   (K transposed)
    __half* Vh = Kt + 64 * P72;      // [64 key][P72]
    __half* Ph = Vh + 64 * P72;      // [64 q][P72]

    const int t    = blockIdx.x;
    const int h    = blockIdx.y;
    const int b    = blockIdx.z;
    const int tid  = threadIdx.x;
    const int lane = tid & 31;
    const int w    = tid >> 5;
    const int r0   = t * 64;

    const size_t base = (size_t)b * SEQ * QKV_LD;

    // ---- stage Q (halves, direct copy) ----
    for (int e = tid; e < 1024; e += 128) {
        const int tok = e >> 4;
        const int d4  = (e & 15) * 4;
        *(uint2*)&Qh[tok * P72 + d4] =
            *(const uint2*)(qkvh + base + (size_t)(r0 + tok) * QKV_LD + h * HDIM + d4);
    }

    const int g  = lane >> 2;
    const int tg = lane & 3;
    const int lrow = lane & 15;
    const int lk8  = (lane & 16) ? 8 : 0;
    const int ln8  = (lane & 16) >> 1;

    float m0 = -3.0e38f, m1 = -3.0e38f, l0 = 0.0f, l1 = 0.0f;
    float o[8][4];
#pragma unroll
    for (int ni = 0; ni < 8; ++ni)
#pragma unroll
        for (int e = 0; e < 4; ++e) o[ni][e] = 0.0f;

    const int kb_start = (t >= 2) ? (t - 2) : 0;
    const int n_win    = t - kb_start + 1;
    const int nglob    = (t >= 3) ? (t - 2) : 0;
    const int n_tiles  = n_win + (nglob > 0 ? 1 : 0);

    const unsigned smQ = (unsigned)__cvta_generic_to_shared(Qh);
    const unsigned smK = (unsigned)__cvta_generic_to_shared(Kt);
    const unsigned smV = (unsigned)__cvta_generic_to_shared(Vh);
    const unsigned smP = (unsigned)__cvta_generic_to_shared(Ph);

    for (int it = 0; it < n_tiles; ++it) {
        const bool is_glob = (it == n_win);
        const int  kcol0   = (kb_start + it) * 64;

        __syncthreads();

        // ---- stage K transposed [d][key] and V natural [key][d] ----
        for (int e = tid; e < 1024; e += 128) {
            const int tok = e >> 4;
            const int d4  = (e & 15) * 4;
            int key;
            bool valid;
            if (is_glob) { key = tok * STRIDE; valid = (tok < nglob); }
            else         { key = kcol0 + tok;  valid = true; }
            uint2 kv, vv;
            if (valid) {
                const __half* kp = qkvh + base + (size_t)key * QKV_LD + DMODEL + h * HDIM + d4;
                kv = *(const uint2*)kp;
                vv = *(const uint2*)(kp + DMODEL);
            } else {
                kv = make_uint2(0u, 0u);
                vv = kv;
            }
            const __half2 k01 = *reinterpret_cast<__half2*>(&kv.x);
            const __half2 k23 = *reinterpret_cast<__half2*>(&kv.y);
            Kt[(d4 + 0) * P72 + tok] = __low2half(k01);
            Kt[(d4 + 1) * P72 + tok] = __high2half(k01);
            Kt[(d4 + 2) * P72 + tok] = __low2half(k23);
            Kt[(d4 + 3) * P72 + tok] = __high2half(k23);
            *(uint2*)&Vh[tok * P72 + d4] = vv;
        }
        __syncthreads();

        // ---- S = Q K^T (fp16 mma, 4 k16 steps) ----
        float s[8][4];
#pragma unroll
        for (int ni = 0; ni < 8; ++ni)
#pragma unroll
            for (int e = 0; e < 4; ++e) s[ni][e] = 0.0f;

#pragma unroll
        for (int ks = 0; ks < 4; ++ks) {
            unsigned a[4];
            unsigned ad = smQ + (((w * 16 + lrow) * P72 + ks * 16 + lk8) << 1);
            asm volatile(
                "ldmatrix.sync.aligned.m8n8.x4.shared.b16 {%0,%1,%2,%3}, [%4];"
                : "=r"(a[0]), "=r"(a[1]), "=r"(a[2]), "=r"(a[3]) : "r"(ad));
            unsigned bf[4][4];
#pragma unroll
            for (int ng = 0; ng < 4; ++ng) {
                unsigned bd = smK + (((ks * 16 + lrow) * P72 + ng * 16 + ln8) << 1);
                asm volatile(
                    "ldmatrix.sync.aligned.m8n8.x4.trans.shared.b16 {%0,%1,%2,%3}, [%4];"
                    : "=r"(bf[ng][0]), "=r"(bf[ng][1]), "=r"(bf[ng][2]), "=r"(bf[ng][3])
                    : "r"(bd));
            }
#pragma unroll
            for (int ni = 0; ni < 8; ++ni) {
                const unsigned b0 = bf[ni >> 1][(ni & 1) * 2];
                const unsigned b1 = bf[ni >> 1][(ni & 1) * 2 + 1];
                asm volatile(
                    "mma.sync.aligned.m16n8k16.row.col.f32.f16.f16.f32 "
                    "{%0,%1,%2,%3}, {%4,%5,%6,%7}, {%8,%9}, {%0,%1,%2,%3};"
                    : "+f"(s[ni][0]), "+f"(s[ni][1]), "+f"(s[ni][2]), "+f"(s[ni][3])
                    : "r"(a[0]), "r"(a[1]), "r"(a[2]), "r"(a[3]), "r"(b0), "r"(b1));
            }
        }

        // ---- mask + scale (base-2 domain) ----
        const int row_lo = r0 + w * 16 + g;
        const int row_hi = row_lo + 8;
#pragma unroll
        for (int ni = 0; ni < 8; ++ni) {
            const int col0 = ni * 8 + 2 * tg;
#pragma unroll
            for (int e = 0; e < 4; ++e) {
                const int col = col0 + (e & 1);
                const int row = (e < 2) ? row_lo : row_hi;
                bool ok;
                if (is_glob) {
                    ok = col < nglob;
                } else {
                    const int c = kcol0 + col;
                    ok = (c <= row) && ((row - c) <= (WINDOW - 1) || (c & (STRIDE - 1)) == 0);
                }
                s[ni][e] = ok ? s[ni][e] * SC2 : -3.0e38f;
            }
        }

        // ---- online softmax ----
        float mx0 = -3.0e38f, mx1 = -3.0e38f;
#pragma unroll
        for (int ni = 0; ni < 8; ++ni) {
            mx0 = fmaxf(mx0, fmaxf(s[ni][0], s[ni][1]));
            mx1 = fmaxf(mx1, fmaxf(s[ni][2], s[ni][3]));
        }
        mx0 = fmaxf(mx0, __shfl_xor_sync(0xffffffffu, mx0, 1));
        mx0 = fmaxf(mx0, __shfl_xor_sync(0xffffffffu, mx0, 2));
        mx1 = fmaxf(mx1, __shfl_xor_sync(0xffffffffu, mx1, 1));
        mx1 = fmaxf(mx1, __shfl_xor_sync(0xffffffffu, mx1, 2));

        const float mn0 = fmaxf(m0, mx0);
        const float mn1 = fmaxf(m1, mx1);
        const float al0 = fexp2(m0 - mn0);
        const float al1 = fexp2(m1 - mn1);

        float rs0 = 0.0f, rs1 = 0.0f;
#pragma unroll
        for (int ni = 0; ni < 8; ++ni) {
            const int col0 = ni * 8 + 2 * tg;
            float p0 = fexp2(s[ni][0] - mn0);
            float p1 = fexp2(s[ni][1] - mn0);
            float p2 = fexp2(s[ni][2] - mn1);
            float p3 = fexp2(s[ni][3] - mn1);
            rs0 += p0 + p1;
            rs1 += p2 + p3;
            *(unsigned*)&Ph[(w * 16 + g) * P72 + col0]     = f2h2(p0, p1);
            *(unsigned*)&Ph[(w * 16 + g + 8) * P72 + col0] = f2h2(p2, p3);
        }
        rs0 += __shfl_xor_sync(0xffffffffu, rs0, 1);
        rs0 += __shfl_xor_sync(0xffffffffu, rs0, 2);
        rs1 += __shfl_xor_sync(0xffffffffu, rs1, 1);
        rs1 += __shfl_xor_sync(0xffffffffu, rs1, 2);

        l0 = l0 * al0 + rs0;
        l1 = l1 * al1 + rs1;
        m0 = mn0;
        m1 = mn1;
#pragma unroll
        for (int ni = 0; ni < 8; ++ni) {
            o[ni][0] *= al0;
            o[ni][1] *= al0;
            o[ni][2] *= al1;
            o[ni][3] *= al1;
        }
        __syncwarp();

        // ---- O += P V (fp16 mma, 4 k16 steps) ----
#pragma unroll
        for (int ks = 0; ks < 4; ++ks) {
            unsigned a[4];
            unsigned ad = smP + (((w * 16 + lrow) * P72 + ks * 16 + lk8) << 1);
            asm volatile(
                "ldmatrix.sync.aligned.m8n8.x4.shared.b16 {%0,%1,%2,%3}, [%4];"
                : "=r"(a[0]), "=r"(a[1]), "=r"(a[2]), "=r"(a[3]) : "r"(ad));
            unsigned bf[4][4];
#pragma unroll
            for (int ng = 0; ng < 4; ++ng) {
                unsigned bd = smV + (((ks * 16 + lrow) * P72 + ng * 16 + ln8) << 1);
                asm volatile(
                    "ldmatrix.sync.aligned.m8n8.x4.trans.shared.b16 {%0,%1,%2,%3}, [%4];"
                    : "=r"(bf[ng][0]), "=r"(bf[ng][1]), "=r"(bf[ng][2]), "=r"(bf[ng][3])
                    : "r"(bd));
            }
#pragma unroll
            for (int ni = 0; ni < 8; ++ni) {
                const unsigned b0 = bf[ni >> 1][(ni & 1) * 2];
                const unsigned b1 = bf[ni >> 1][(ni & 1) * 2 + 1];
                asm volatile(
                    "mma.sync.aligned.m16n8k16.row.col.f32.f16.f16.f32 "
                    "{%0,%1,%2,%3}, {%4,%5,%6,%7}, {%8,%9}, {%0,%1,%2,%3};"
                    : "+f"(o[ni][0]), "+f"(o[ni][1]), "+f"(o[ni][2]), "+f"(o[ni][3])
                    : "r"(a[0]), "r"(a[1]), "r"(a[2]), "r"(a[3]), "r"(b0), "r"(b1));
            }
        }
        __syncwarp();
    }

    // ---- epilogue: normalize + write y (half) ----
    const float inv0 = 1.0f / l0;
    const float inv1 = 1.0f / l1;
    const size_t row_lo = (size_t)b * SEQ + r0 + w * 16 + g;
#pragma unroll
    for (int ni = 0; ni < 8; ++ni) {
        const int col = h * HDIM + ni * 8 + 2 * tg;
        *(unsigned*)&yh[row_lo * DMODEL + col] =
            f2h2(o[ni][0] * inv0, o[ni][1] * inv0);
        *(unsigned*)&yh[(row_lo + 8) * DMODEL + col] =
            f2h2(o[ni][2] * inv1, o[ni][3] * inv1);
    }
}

// ---------------------------------------------------------------------------
extern "C" void kernel_launch(void* const* d_in, const int* in_sizes, int n_in,
                              void* d_out, int out_size)
{
    const float* x     = (const float*)d_in[0];
    const float* Wqkv  = (const float*)d_in[1];
    const float* Wproj = (const float*)d_in[2];
    float* out = (float*)d_out;

    __half *xh = nullptr, *wqkvh = nullptr, *wph = nullptr, *qkvh = nullptr, *yh = nullptr;
    cudaGetSymbolAddress((void**)&xh, g_xh);
    cudaGetSymbolAddress((void**)&wqkvh, g_wqkvh);
    cudaGetSymbolAddress((void**)&wph, g_wph);
    cudaGetSymbolAddress((void**)&qkvh, g_qkvh);
    cudaGetSymbolAddress((void**)&yh, g_yh);

    cudaFuncSetAttribute(hgemm<__half>, cudaFuncAttributeMaxDynamicSharedMemorySize, GEMM_SMEM);
    cudaFuncSetAttribute(hgemm<float>,  cudaFuncAttributeMaxDynamicSharedMemorySize, GEMM_SMEM);
    cudaFuncSetAttribute(sparse_attn,   cudaFuncAttributeMaxDynamicSharedMemorySize, ATTN_SMEM);

    // 0) fp32 -> fp16 convert (one kernel)
    cvt_all<<<2048, 256>>>(
        (const float4*)x,     (uint2*)xh,    NTOK * DMODEL / 4,
        (const float4*)Wqkv,  (uint2*)wqkvh, DMODEL * QKV_LD / 4,
        (const float4*)Wproj, (uint2*)wph,   DMODEL * DMODEL / 4);

    // 1) QKV projection: [4096,1024] @ [1024,3072] -> half qkv
    hgemm<__half><<<dim3(QKV_LD / BNh, NTOK / BMh), 256, GEMM_SMEM>>>(
        xh, wqkvh, qkvh, NTOK, QKV_LD, DMODEL);

    // 2) Sparse attention (fp16 tensor cores) -> half y
    sparse_attn<<<dim3(SEQ / 64, NHEADS, BATCH), 128, ATTN_SMEM>>>(qkvh, yh);

    // 3) Output projection: [4096,1024] @ [1024,1024] -> fp32 out
    hgemm<float><<<dim3(DMODEL / BNh, NTOK / BMh), 256, GEMM_SMEM>>>(
        yh, wph, out, NTOK, DMODEL, DMODEL);
}